// round 1
// baseline (speedup 1.0000x reference)
#include <cuda_runtime.h>

#define LATENT 64
#define OUT    128
#define H      32
#define BM     128
#define TK     32
#define APAD   36
#define BPAD   132

// Scratch (no device allocation allowed)
__device__ float g_sp[OUT];
__device__ float g_sn[OUT];
__device__ int   g_slow;

// ---------------------------------------------------------------------------
// Precompute: per-feature collapsed slopes sp/sn (valid when b1==b2==0),
// and set g_slow if any b1/b2 entry is nonzero.
//   sp[d] = W3[d] . relu(W2[d] @ relu( W1[d]))
//   sn[d] = W3[d] . relu(W2[d] @ relu(-W1[d]))
// ---------------------------------------------------------------------------
__global__ void precompute_kernel(const float* __restrict__ W1,
                                  const float* __restrict__ b1,
                                  const float* __restrict__ W2,
                                  const float* __restrict__ b2,
                                  const float* __restrict__ W3)
{
    int d = threadIdx.x;            // 128 threads, one feature each
    if (d == 0) g_slow = 0;
    __syncthreads();

    float rp[H], rn[H];
    int nz = 0;
#pragma unroll
    for (int h = 0; h < H; ++h) {
        float w = W1[d * H + h];
        rp[h] = fmaxf(w, 0.f);
        rn[h] = fmaxf(-w, 0.f);
        nz |= (b1[d * H + h] != 0.f);
    }

    float sp = 0.f, sn = 0.f;
#pragma unroll 4
    for (int k = 0; k < H; ++k) {
        float up = 0.f, un = 0.f;
        const float* w2row = W2 + ((long)d * H + k) * H;
#pragma unroll
        for (int h = 0; h < H; ++h) {
            float w = w2row[h];
            up = fmaf(w, rp[h], up);
            un = fmaf(w, rn[h], un);
        }
        float w3 = W3[d * H + k];
        sp = fmaf(w3, fmaxf(up, 0.f), sp);
        sn = fmaf(w3, fmaxf(un, 0.f), sn);
        nz |= (b2[d * H + k] != 0.f);
    }
    g_sp[d] = sp;
    g_sn[d] = sn;
    if (nz) atomicOr(&g_slow, 1);
}

// ---------------------------------------------------------------------------
// Main: y = z @ |Wp|^T tiled fp32 GEMM (BMx128, K=64), fused epilogue
//   out[n,d] = | |y| * (y>0 ? sp[d] : sn[d]) + b3[d] |
// 256 threads, 8x8 register tile per thread.
// ---------------------------------------------------------------------------
__global__ __launch_bounds__(256, 2) void main_kernel(
    const float* __restrict__ z, const float* __restrict__ Wp,
    const float* __restrict__ b3, float* __restrict__ out)
{
    if (g_slow) return;

    __shared__ __align__(16) float As[BM][APAD];   // [row][k] padded
    __shared__ __align__(16) float Bs[TK][BPAD];   // [k][d]  padded

    const int tid   = threadIdx.x;
    const int row_t = tid >> 4;
    const int col_t = tid & 15;
    const int row0  = row_t * 8;
    const int col0  = col_t * 8;
    const int brow  = blockIdx.x * BM;

    float acc[8][8];
#pragma unroll
    for (int i = 0; i < 8; ++i)
#pragma unroll
        for (int j = 0; j < 8; ++j) acc[i][j] = 0.f;

#pragma unroll 1
    for (int k0 = 0; k0 < LATENT; k0 += TK) {
        // Load A chunk: BM x TK from z (row-major), vectorized
#pragma unroll
        for (int t = 0; t < 4; ++t) {
            int idx = tid + t * 256;      // over 128 rows x 8 float4
            int r   = idx >> 3;
            int kq  = idx & 7;
            float4 v = *(const float4*)(z + (long)(brow + r) * LATENT + k0 + kq * 4);
            *(float4*)&As[r][kq * 4] = v;
        }
        // Load B chunk: |Wp[d][k0..k0+31]| transposed into Bs[k][d]
#pragma unroll
        for (int t = 0; t < 4; ++t) {
            int idx = tid + t * 256;      // over 128 d x 8 float4
            int d   = idx >> 3;
            int kq  = idx & 7;
            float4 v = *(const float4*)(Wp + (long)d * LATENT + k0 + kq * 4);
            Bs[kq * 4 + 0][d] = fabsf(v.x);
            Bs[kq * 4 + 1][d] = fabsf(v.y);
            Bs[kq * 4 + 2][d] = fabsf(v.z);
            Bs[kq * 4 + 3][d] = fabsf(v.w);
        }
        __syncthreads();

#pragma unroll 8
        for (int k = 0; k < TK; ++k) {
            float a[8], b[8];
#pragma unroll
            for (int i = 0; i < 8; ++i) a[i] = As[row0 + i][k];
            *(float4*)&b[0] = *(const float4*)&Bs[k][col0];
            *(float4*)&b[4] = *(const float4*)&Bs[k][col0 + 4];
#pragma unroll
            for (int i = 0; i < 8; ++i)
#pragma unroll
                for (int j = 0; j < 8; ++j)
                    acc[i][j] = fmaf(a[i], b[j], acc[i][j]);
        }
        __syncthreads();
    }

    // Fused epilogue
    float spv[8], snv[8], b3v[8];
#pragma unroll
    for (int j = 0; j < 8; ++j) {
        spv[j] = g_sp[col0 + j];
        snv[j] = g_sn[col0 + j];
        b3v[j] = b3[col0 + j];
    }
#pragma unroll
    for (int i = 0; i < 8; ++i) {
        float r[8];
#pragma unroll
        for (int j = 0; j < 8; ++j) {
            float y = acc[i][j];
            float s = (y > 0.f) ? spv[j] : snv[j];
            r[j] = fabsf(fmaf(fabsf(y), s, b3v[j]));
        }
        float* o = out + (long)(brow + row0 + i) * OUT + col0;
        *(float4*)o       = make_float4(r[0], r[1], r[2], r[3]);
        *(float4*)(o + 4) = make_float4(r[4], r[5], r[6], r[7]);
    }
}

// ---------------------------------------------------------------------------
// Fallback: full per-element MLP, only runs if any b1/b2 is nonzero.
// Grid-stride so the no-op case costs ~nothing.
// ---------------------------------------------------------------------------
__global__ void fallback_kernel(const float* __restrict__ z,  const float* __restrict__ Wp,
                                const float* __restrict__ W1, const float* __restrict__ b1,
                                const float* __restrict__ W2, const float* __restrict__ b2,
                                const float* __restrict__ W3, const float* __restrict__ b3,
                                float* __restrict__ out, long total)
{
    if (!g_slow) return;
    for (long idx = (long)blockIdx.x * blockDim.x + threadIdx.x; idx < total;
         idx += (long)gridDim.x * blockDim.x) {
        int n = (int)(idx >> 7);
        int d = (int)(idx & (OUT - 1));
        float y = 0.f;
#pragma unroll
        for (int k = 0; k < LATENT; ++k)
            y = fmaf(z[(long)n * LATENT + k], fabsf(Wp[d * LATENT + k]), y);
        float h1[H];
#pragma unroll
        for (int h = 0; h < H; ++h)
            h1[h] = fmaxf(fmaf(y, W1[d * H + h], b1[d * H + h]), 0.f);
        float x = b3[d];
#pragma unroll 4
        for (int k = 0; k < H; ++k) {
            float t = b2[d * H + k];
            const float* w2 = W2 + ((long)d * H + k) * H;
#pragma unroll
            for (int h = 0; h < H; ++h) t = fmaf(w2[h], h1[h], t);
            x = fmaf(W3[d * H + k], fmaxf(t, 0.f), x);
        }
        out[idx] = fabsf(x);
    }
}

// ---------------------------------------------------------------------------
extern "C" void kernel_launch(void* const* d_in, const int* in_sizes, int n_in,
                              void* d_out, int out_size)
{
    const float* z  = (const float*)d_in[0];
    const float* Wp = (const float*)d_in[1];
    const float* W1 = (const float*)d_in[2];
    const float* b1 = (const float*)d_in[3];
    const float* W2 = (const float*)d_in[4];
    const float* b2 = (const float*)d_in[5];
    const float* W3 = (const float*)d_in[6];
    const float* b3 = (const float*)d_in[7];
    float* out = (float*)d_out;

    int nrows = in_sizes[0] / LATENT;   // 65536

    precompute_kernel<<<1, OUT>>>(W1, b1, W2, b2, W3);
    main_kernel<<<nrows / BM, 256>>>(z, Wp, b3, out);
    fallback_kernel<<<148 * 4, 256>>>(z, Wp, W1, b1, W2, b2, W3, b3, out,
                                      (long)nrows * OUT);
}

// round 2
// speedup vs baseline: 2.5912x; 2.5912x over previous
#include <cuda_runtime.h>
#include <cstdint>

#define LATENT 64
#define OUT    128
#define H      32
#define BM     128
#define TK     32
#define APAD   36
#define BPAD   132

// Scratch (no device allocation allowed)
__device__ float g_sp[OUT];
__device__ float g_sn[OUT];
__device__ int   g_slow = 0;

// Packed f32x2 helpers (Blackwell FFMA2 — only reachable via PTX)
#define FMA_F32X2(d, a, b, c) \
    asm("fma.rn.f32x2 %0, %1, %2, %3;" : "=l"(d) : "l"(a), "l"(b), "l"(c))
#define PACK_F32X2(out, lo, hi) \
    asm("mov.b64 %0, {%1, %2};" : "=l"(out) : "r"(lo), "r"(hi))
#define UNPACK_F32X2(lo, hi, in) \
    asm("mov.b64 {%0, %1}, %2;" : "=r"(lo), "=r"(hi) : "l"(in))

// ---------------------------------------------------------------------------
// Precompute: per-feature collapsed slopes sp/sn (valid when b1==b2==0).
// One warp per feature d. Lane k handles W2[d,k,:]; W1[d,:] broadcast by shfl.
//   sp[d] = W3[d] . relu(W2[d] @ relu( W1[d]))
//   sn[d] = W3[d] . relu(W2[d] @ relu(-W1[d]))
// Sets g_slow if any b1/b2 entry is nonzero (sticky across graph replays —
// inputs are constant per run, so this stays deterministic).
// ---------------------------------------------------------------------------
__global__ void precompute_kernel(const float* __restrict__ W1,
                                  const float* __restrict__ b1,
                                  const float* __restrict__ W2,
                                  const float* __restrict__ b2,
                                  const float* __restrict__ W3)
{
    const int d    = blockIdx.x;     // 128 blocks
    const int lane = threadIdx.x;    // 32 lanes

    float w1v  = W1[d * H + lane];
    int   nz   = (b1[d * H + lane] != 0.f) | (b2[d * H + lane] != 0.f);

    const float4* w2 = (const float4*)(W2 + ((long)d * H + lane) * H);
    float up = 0.f, un = 0.f;
#pragma unroll
    for (int q = 0; q < H / 4; ++q) {
        float4 w = w2[q];
        float wv[4] = {w.x, w.y, w.z, w.w};
#pragma unroll
        for (int j = 0; j < 4; ++j) {
            float w1h = __shfl_sync(0xffffffffu, w1v, q * 4 + j);
            up = fmaf(wv[j], fmaxf(w1h, 0.f), up);
            un = fmaf(wv[j], fmaxf(-w1h, 0.f), un);
        }
    }
    float w3 = W3[d * H + lane];
    float tp = w3 * fmaxf(up, 0.f);
    float tn = w3 * fmaxf(un, 0.f);

#pragma unroll
    for (int off = 16; off > 0; off >>= 1) {
        tp += __shfl_down_sync(0xffffffffu, tp, off);
        tn += __shfl_down_sync(0xffffffffu, tn, off);
    }
    unsigned any_nz = __ballot_sync(0xffffffffu, nz);
    if (lane == 0) {
        g_sp[d] = tp;
        g_sn[d] = tn;
        if (any_nz) atomicOr(&g_slow, 1);
    }
}

// ---------------------------------------------------------------------------
// Main: y = z @ |Wp|^T tiled fp32 GEMM (BMx128, K=64) with packed FFMA2
// inner loop, fused epilogue:
//   out[n,d] = | |y| * (y>0 ? sp[d] : sn[d]) + b3[d] |
// 256 threads, 8x8 register tile per thread (accumulators packed pairwise
// along the feature dim so b-pairs come straight from LDS.128).
// ---------------------------------------------------------------------------
__global__ __launch_bounds__(256, 2) void main_kernel(
    const float* __restrict__ z, const float* __restrict__ Wp,
    const float* __restrict__ b3, float* __restrict__ out)
{
    if (g_slow) return;

    __shared__ __align__(16) float As[BM][APAD];   // [row][k] padded
    __shared__ __align__(16) float Bs[TK][BPAD];   // [k][d]  padded

    const int tid   = threadIdx.x;
    const int row_t = tid >> 4;
    const int col_t = tid & 15;
    const int row0  = row_t * 8;
    const int col0  = col_t * 8;
    const int brow  = blockIdx.x * BM;

    unsigned long long accp[8][4];                 // (acc[i][2jp], acc[i][2jp+1])
#pragma unroll
    for (int i = 0; i < 8; ++i)
#pragma unroll
        for (int jp = 0; jp < 4; ++jp) accp[i][jp] = 0ull;

#pragma unroll 1
    for (int k0 = 0; k0 < LATENT; k0 += TK) {
        // Load A chunk: BM x TK from z (row-major), vectorized
#pragma unroll
        for (int t = 0; t < 4; ++t) {
            int idx = tid + t * 256;      // over 128 rows x 8 float4
            int r   = idx >> 3;
            int kq  = idx & 7;
            float4 v = *(const float4*)(z + (long)(brow + r) * LATENT + k0 + kq * 4);
            *(float4*)&As[r][kq * 4] = v;
        }
        // Load B chunk: |Wp[d][k0..k0+31]| transposed into Bs[k][d]
#pragma unroll
        for (int t = 0; t < 4; ++t) {
            int idx = tid + t * 256;      // over 128 d x 8 float4
            int d   = idx >> 3;
            int kq  = idx & 7;
            float4 v = *(const float4*)(Wp + (long)d * LATENT + k0 + kq * 4);
            Bs[kq * 4 + 0][d] = fabsf(v.x);
            Bs[kq * 4 + 1][d] = fabsf(v.y);
            Bs[kq * 4 + 2][d] = fabsf(v.z);
            Bs[kq * 4 + 3][d] = fabsf(v.w);
        }
        __syncthreads();

#pragma unroll 8
        for (int k = 0; k < TK; ++k) {
            // b pairs: 2x LDS.128, reinterpret as 4 packed f32x2
            unsigned long long bp[4];
            float4 bv0 = *(const float4*)&Bs[k][col0];
            float4 bv1 = *(const float4*)&Bs[k][col0 + 4];
            PACK_F32X2(bp[0], __float_as_uint(bv0.x), __float_as_uint(bv0.y));
            PACK_F32X2(bp[1], __float_as_uint(bv0.z), __float_as_uint(bv0.w));
            PACK_F32X2(bp[2], __float_as_uint(bv1.x), __float_as_uint(bv1.y));
            PACK_F32X2(bp[3], __float_as_uint(bv1.z), __float_as_uint(bv1.w));

#pragma unroll
            for (int i = 0; i < 8; ++i) {
                float a = As[row0 + i][k];           // broadcast LDS
                unsigned long long ad;
                PACK_F32X2(ad, __float_as_uint(a), __float_as_uint(a));
#pragma unroll
                for (int jp = 0; jp < 4; ++jp)
                    FMA_F32X2(accp[i][jp], ad, bp[jp], accp[i][jp]);
            }
        }
        __syncthreads();
    }

    // Fused epilogue
    float spv[8], snv[8], b3v[8];
#pragma unroll
    for (int j = 0; j < 8; ++j) {
        spv[j] = g_sp[col0 + j];
        snv[j] = g_sn[col0 + j];
        b3v[j] = b3[col0 + j];
    }
#pragma unroll
    for (int i = 0; i < 8; ++i) {
        float r[8];
#pragma unroll
        for (int jp = 0; jp < 4; ++jp) {
            unsigned lo, hi;
            UNPACK_F32X2(lo, hi, accp[i][jp]);
            float y0 = __uint_as_float(lo);
            float y1 = __uint_as_float(hi);
            float s0 = (y0 > 0.f) ? spv[2 * jp]     : snv[2 * jp];
            float s1 = (y1 > 0.f) ? spv[2 * jp + 1] : snv[2 * jp + 1];
            r[2 * jp]     = fabsf(fmaf(fabsf(y0), s0, b3v[2 * jp]));
            r[2 * jp + 1] = fabsf(fmaf(fabsf(y1), s1, b3v[2 * jp + 1]));
        }
        float* o = out + (long)(brow + row0 + i) * OUT + col0;
        *(float4*)o       = make_float4(r[0], r[1], r[2], r[3]);
        *(float4*)(o + 4) = make_float4(r[4], r[5], r[6], r[7]);
    }
}

// ---------------------------------------------------------------------------
// Fallback: full per-element MLP, only runs if any b1/b2 is nonzero.
// ---------------------------------------------------------------------------
__global__ void fallback_kernel(const float* __restrict__ z,  const float* __restrict__ Wp,
                                const float* __restrict__ W1, const float* __restrict__ b1,
                                const float* __restrict__ W2, const float* __restrict__ b2,
                                const float* __restrict__ W3, const float* __restrict__ b3,
                                float* __restrict__ out, long total)
{
    if (!g_slow) return;
    for (long idx = (long)blockIdx.x * blockDim.x + threadIdx.x; idx < total;
         idx += (long)gridDim.x * blockDim.x) {
        int n = (int)(idx >> 7);
        int d = (int)(idx & (OUT - 1));
        float y = 0.f;
#pragma unroll
        for (int k = 0; k < LATENT; ++k)
            y = fmaf(z[(long)n * LATENT + k], fabsf(Wp[d * LATENT + k]), y);
        float h1[H];
#pragma unroll
        for (int h = 0; h < H; ++h)
            h1[h] = fmaxf(fmaf(y, W1[d * H + h], b1[d * H + h]), 0.f);
        float x = b3[d];
#pragma unroll 4
        for (int k = 0; k < H; ++k) {
            float t = b2[d * H + k];
            const float* w2 = W2 + ((long)d * H + k) * H;
#pragma unroll
            for (int h = 0; h < H; ++h) t = fmaf(w2[h], h1[h], t);
            x = fmaf(W3[d * H + k], fmaxf(t, 0.f), x);
        }
        out[idx] = fabsf(x);
    }
}

// ---------------------------------------------------------------------------
extern "C" void kernel_launch(void* const* d_in, const int* in_sizes, int n_in,
                              void* d_out, int out_size)
{
    const float* z  = (const float*)d_in[0];
    const float* Wp = (const float*)d_in[1];
    const float* W1 = (const float*)d_in[2];
    const float* b1 = (const float*)d_in[3];
    const float* W2 = (const float*)d_in[4];
    const float* b2 = (const float*)d_in[5];
    const float* W3 = (const float*)d_in[6];
    const float* b3 = (const float*)d_in[7];
    float* out = (float*)d_out;

    int nrows = in_sizes[0] / LATENT;   // 65536

    precompute_kernel<<<OUT, 32>>>(W1, b1, W2, b2, W3);
    main_kernel<<<nrows / BM, 256>>>(z, Wp, b3, out);
    fallback_kernel<<<148 * 4, 256>>>(z, Wp, W1, b1, W2, b2, W3, b3, out,
                                      (long)nrows * OUT);
}

// round 4
// speedup vs baseline: 3.9826x; 1.5370x over previous
#include <cuda_runtime.h>
#include <cuda_bf16.h>
#include <cstdint>

#define LATENT 64
#define OUT    128
#define H      32
#define BM     128
#define PITCH  144   // bytes per smem tile row (72 bf16) — conflict-free ldmatrix

// smem layout (dynamic)
#define SM_SP   0
#define SM_SN   512
#define SM_B3   1024
#define SM_AHI  1536
#define SM_ALO  (SM_AHI + BM * PITCH)     // 19968
#define SM_BHI  (SM_ALO + BM * PITCH)     // 38400
#define SM_BLO  (SM_BHI + OUT * PITCH)    // 56832
#define SM_TOTAL (SM_BLO + OUT * PITCH)   // 75264

// Scratch (no device allocation allowed)
__device__ float g_sp[OUT];
__device__ float g_sn[OUT];
__device__ int   g_slow = 0;
__device__ __align__(16) unsigned short g_bhi[OUT * LATENT];
__device__ __align__(16) unsigned short g_blo[OUT * LATENT];

// ---------------------------------------------------------------------------
// PTX helpers (family-portable only: ldmatrix + mma.sync, no tcgen05)
// ---------------------------------------------------------------------------
__device__ __forceinline__ uint32_t smem_u32(const void* p) {
    uint32_t a;
    asm("{ .reg .u64 t; cvta.to.shared.u64 t, %1; cvt.u32.u64 %0, t; }"
        : "=r"(a) : "l"(p));
    return a;
}
#define LDSM_X4(r0, r1, r2, r3, addr)                                          \
    asm volatile("ldmatrix.sync.aligned.m8n8.x4.shared.b16 {%0,%1,%2,%3}, [%4];" \
                 : "=r"(r0), "=r"(r1), "=r"(r2), "=r"(r3) : "r"(addr))
#define LDSM_X2(r0, r1, addr)                                                  \
    asm volatile("ldmatrix.sync.aligned.m8n8.x2.shared.b16 {%0,%1}, [%2];"     \
                 : "=r"(r0), "=r"(r1) : "r"(addr))
#define MMA_BF16(c, a, b)                                                      \
    asm volatile("mma.sync.aligned.m16n8k16.row.col.f32.bf16.bf16.f32 "        \
                 "{%0,%1,%2,%3},{%4,%5,%6,%7},{%8,%9},{%0,%1,%2,%3};"          \
                 : "+f"((c)[0]), "+f"((c)[1]), "+f"((c)[2]), "+f"((c)[3])      \
                 : "r"((a)[0]), "r"((a)[1]), "r"((a)[2]), "r"((a)[3]),         \
                   "r"((b)[0]), "r"((b)[1]))

__device__ __forceinline__ unsigned pack_bf16(float a, float b) {
    __nv_bfloat162 t = __floats2bfloat162_rn(a, b);
    return *(unsigned*)&t;
}

// ---------------------------------------------------------------------------
// Precompute: collapsed slopes sp/sn (valid when b1==b2==0; sets g_slow
// otherwise) AND the bf16 hi/lo split of |Wp| into g_bhi/g_blo.
// One warp per feature d.
// ---------------------------------------------------------------------------
__global__ void precompute_kernel(const float* __restrict__ Wp,
                                  const float* __restrict__ W1,
                                  const float* __restrict__ b1,
                                  const float* __restrict__ W2,
                                  const float* __restrict__ b2,
                                  const float* __restrict__ W3)
{
    const int d    = blockIdx.x;
    const int lane = threadIdx.x;

    // bf16 split of |Wp[d]| (2 elems per lane)
#pragma unroll
    for (int j = 0; j < 2; ++j) {
        int k = lane * 2 + j;
        float w = fabsf(Wp[d * LATENT + k]);
        __nv_bfloat16 hi = __float2bfloat16_rn(w);
        float lo = w - __bfloat162float(hi);
        g_bhi[d * LATENT + k] = __bfloat16_as_ushort(hi);
        g_blo[d * LATENT + k] = __bfloat16_as_ushort(__float2bfloat16_rn(lo));
    }

    float w1v = W1[d * H + lane];
    int   nz  = (b1[d * H + lane] != 0.f) | (b2[d * H + lane] != 0.f);

    const float4* w2 = (const float4*)(W2 + ((long)d * H + lane) * H);
    float up = 0.f, un = 0.f;
#pragma unroll
    for (int q = 0; q < H / 4; ++q) {
        float4 w = w2[q];
        float wv[4] = {w.x, w.y, w.z, w.w};
#pragma unroll
        for (int j = 0; j < 4; ++j) {
            float w1h = __shfl_sync(0xffffffffu, w1v, q * 4 + j);
            up = fmaf(wv[j], fmaxf(w1h, 0.f), up);
            un = fmaf(wv[j], fmaxf(-w1h, 0.f), un);
        }
    }
    float w3 = W3[d * H + lane];
    float tp = w3 * fmaxf(up, 0.f);
    float tn = w3 * fmaxf(un, 0.f);
#pragma unroll
    for (int off = 16; off > 0; off >>= 1) {
        tp += __shfl_down_sync(0xffffffffu, tp, off);
        tn += __shfl_down_sync(0xffffffffu, tn, off);
    }
    unsigned any_nz = __ballot_sync(0xffffffffu, nz);
    if (lane == 0) {
        g_sp[d] = tp;
        g_sn[d] = tn;
        if (any_nz) atomicOr(&g_slow, 1);
    }
}

// ---------------------------------------------------------------------------
// Main: bf16x3 mma.sync GEMM (BM=128 x 128, K=64) + fused epilogue
//   out[n,d] = | |y| * (y>0 ? sp[d] : sn[d]) + b3[d] |
// 8 warps, warp tile 64(m) x 32(n); m16n8k16 fragments via ldmatrix.
// ---------------------------------------------------------------------------
__global__ __launch_bounds__(256, 2) void main_kernel(
    const float* __restrict__ z, const float* __restrict__ b3,
    float* __restrict__ out)
{
    if (g_slow) return;

    extern __shared__ char smem[];
    const uint32_t sb = smem_u32(smem);
    const int tid  = threadIdx.x;
    const int wid  = tid >> 5;
    const int lane = tid & 31;
    const int wm   = wid >> 2;   // 0..1 -> rows wm*64
    const int wn   = wid & 3;    // 0..3 -> cols wn*32
    const int brow = blockIdx.x * BM;

    // Stage epilogue constants
    if (tid < OUT) {
        ((float*)(smem + SM_SP))[tid] = g_sp[tid];
        ((float*)(smem + SM_SN))[tid] = g_sn[tid];
        ((float*)(smem + SM_B3))[tid] = b3[tid];
    }

    // Load z tile (128 x 64 fp32), split to bf16 hi/lo in smem.
    // Thread t: row = t>>1, 32 floats starting at k = (t&1)*32.
    {
        const int row  = tid >> 1;
        const int half = tid & 1;
        const float4* zr = (const float4*)(z + (size_t)(brow + row) * LATENT + half * 32);
#pragma unroll
        for (int j = 0; j < 4; ++j) {
            float4 v0 = zr[j * 2];
            float4 v1 = zr[j * 2 + 1];
            float f[8] = {v0.x, v0.y, v0.z, v0.w, v1.x, v1.y, v1.z, v1.w};
            float hi[8], lo[8];
#pragma unroll
            for (int e = 0; e < 8; ++e) {
                hi[e] = __bfloat162float(__float2bfloat16_rn(f[e]));
                lo[e] = f[e] - hi[e];
            }
            uint4 uh, ul;
            uh.x = pack_bf16(hi[0], hi[1]); uh.y = pack_bf16(hi[2], hi[3]);
            uh.z = pack_bf16(hi[4], hi[5]); uh.w = pack_bf16(hi[6], hi[7]);
            ul.x = pack_bf16(lo[0], lo[1]); ul.y = pack_bf16(lo[2], lo[3]);
            ul.z = pack_bf16(lo[4], lo[5]); ul.w = pack_bf16(lo[6], lo[7]);
            int off = row * PITCH + (half * 32 + j * 8) * 2;
            *(uint4*)(smem + SM_AHI + off) = uh;
            *(uint4*)(smem + SM_ALO + off) = ul;
        }
    }
    // Load B hi/lo (precomputed |Wp| split) from device arrays (L2-hot).
    {
        const uint4* bh = (const uint4*)g_bhi;
        const uint4* bl = (const uint4*)g_blo;
#pragma unroll
        for (int i = 0; i < 4; ++i) {
            int idx = tid + i * 256;        // 1024 uint4 total
            int row = idx >> 3;
            int seg = idx & 7;
            int off = row * PITCH + seg * 16;
            *(uint4*)(smem + SM_BHI + off) = bh[idx];
            *(uint4*)(smem + SM_BLO + off) = bl[idx];
        }
    }
    __syncthreads();

    // ldmatrix lane base addresses
    const uint32_t aoff = sb + (uint32_t)((wm * 64 + (lane & 15)) * PITCH +
                                          ((lane >> 4) * 8) * 2);
    const uint32_t boff = sb + (uint32_t)((wn * 32 + (lane & 7)) * PITCH +
                                          (((lane >> 3) & 1) * 8) * 2);

    float acc[4][4][4];
#pragma unroll
    for (int f = 0; f < 4; ++f)
#pragma unroll
        for (int g = 0; g < 4; ++g)
#pragma unroll
            for (int e = 0; e < 4; ++e) acc[f][g][e] = 0.f;

#pragma unroll
    for (int term = 0; term < 3; ++term) {
        const uint32_t ab = aoff + (term == 1 ? SM_ALO : SM_AHI);
        const uint32_t bb = boff + (term == 2 ? SM_BLO : SM_BHI);
#pragma unroll
        for (int s = 0; s < 4; ++s) {        // K=64 in 4 k16 steps
            uint32_t a[4][4], b[4][2];
#pragma unroll
            for (int f = 0; f < 4; ++f)
                LDSM_X4(a[f][0], a[f][1], a[f][2], a[f][3],
                        ab + f * 16 * PITCH + s * 32);
#pragma unroll
            for (int g = 0; g < 4; ++g)
                LDSM_X2(b[g][0], b[g][1], bb + g * 8 * PITCH + s * 32);
#pragma unroll
            for (int f = 0; f < 4; ++f)
#pragma unroll
                for (int g = 0; g < 4; ++g)
                    MMA_BF16(acc[f][g], a[f], b[g]);
        }
    }

    // Fused epilogue straight from fragments.
    // c0:(m=l/4, n=2(l%4)) c1:n+1 c2:(m+8,n) c3:(m+8,n+1)
    {
        const int qrow = lane >> 2;
        const int qcol = 2 * (lane & 3);
        const float* sps = (const float*)(smem + SM_SP);
        const float* sns = (const float*)(smem + SM_SN);
        const float* b3s = (const float*)(smem + SM_B3);
#pragma unroll
        for (int g = 0; g < 4; ++g) {
            const int c0 = wn * 32 + g * 8 + qcol;
            float sp0 = sps[c0], sp1 = sps[c0 + 1];
            float sn0 = sns[c0], sn1 = sns[c0 + 1];
            float t0  = b3s[c0], t1  = b3s[c0 + 1];
#pragma unroll
            for (int f = 0; f < 4; ++f) {
                const int r0 = brow + wm * 64 + f * 16 + qrow;
                float y0 = acc[f][g][0], y1 = acc[f][g][1];
                float y2 = acc[f][g][2], y3 = acc[f][g][3];
                float o0 = fabsf(fmaf(fabsf(y0), (y0 > 0.f ? sp0 : sn0), t0));
                float o1 = fabsf(fmaf(fabsf(y1), (y1 > 0.f ? sp1 : sn1), t1));
                float o2 = fabsf(fmaf(fabsf(y2), (y2 > 0.f ? sp0 : sn0), t0));
                float o3 = fabsf(fmaf(fabsf(y3), (y3 > 0.f ? sp1 : sn1), t1));
                *(float2*)(out + (size_t)r0 * OUT + c0)       = make_float2(o0, o1);
                *(float2*)(out + (size_t)(r0 + 8) * OUT + c0) = make_float2(o2, o3);
            }
        }
    }
}

// ---------------------------------------------------------------------------
// Fallback: full per-element MLP, only runs if any b1/b2 is nonzero.
// ---------------------------------------------------------------------------
__global__ void fallback_kernel(const float* __restrict__ z,  const float* __restrict__ Wp,
                                const float* __restrict__ W1, const float* __restrict__ b1,
                                const float* __restrict__ W2, const float* __restrict__ b2,
                                const float* __restrict__ W3, const float* __restrict__ b3,
                                float* __restrict__ out, long total)
{
    if (!g_slow) return;
    for (long idx = (long)blockIdx.x * blockDim.x + threadIdx.x; idx < total;
         idx += (long)gridDim.x * blockDim.x) {
        int n = (int)(idx >> 7);
        int d = (int)(idx & (OUT - 1));
        float y = 0.f;
#pragma unroll
        for (int k = 0; k < LATENT; ++k)
            y = fmaf(z[(long)n * LATENT + k], fabsf(Wp[d * LATENT + k]), y);
        float h1[H];
#pragma unroll
        for (int h = 0; h < H; ++h)
            h1[h] = fmaxf(fmaf(y, W1[d * H + h], b1[d * H + h]), 0.f);
        float x = b3[d];
#pragma unroll 4
        for (int k = 0; k < H; ++k) {
            float t = b2[d * H + k];
            const float* w2 = W2 + ((long)d * H + k) * H;
#pragma unroll
            for (int h = 0; h < H; ++h) t = fmaf(w2[h], h1[h], t);
            x = fmaf(W3[d * H + k], fmaxf(t, 0.f), x);
        }
        out[idx] = fabsf(x);
    }
}

// ---------------------------------------------------------------------------
extern "C" void kernel_launch(void* const* d_in, const int* in_sizes, int n_in,
                              void* d_out, int out_size)
{
    const float* z  = (const float*)d_in[0];
    const float* Wp = (const float*)d_in[1];
    const float* W1 = (const float*)d_in[2];
    const float* b1 = (const float*)d_in[3];
    const float* W2 = (const float*)d_in[4];
    const float* b2 = (const float*)d_in[5];
    const float* W3 = (const float*)d_in[6];
    const float* b3 = (const float*)d_in[7];
    float* out = (float*)d_out;

    int nrows = in_sizes[0] / LATENT;   // 65536

    cudaFuncSetAttribute(main_kernel,
                         cudaFuncAttributeMaxDynamicSharedMemorySize, SM_TOTAL);

    precompute_kernel<<<OUT, 32>>>(Wp, W1, b1, W2, b2, W3);
    main_kernel<<<nrows / BM, 256, SM_TOTAL>>>(z, b3, out);
    fallback_kernel<<<148 * 4, 256>>>(z, Wp, W1, b1, W2, b2, W3, b3, out,
                                      (long)nrows * OUT);
}

// round 5
// speedup vs baseline: 5.0889x; 1.2778x over previous
#include <cuda_runtime.h>
#include <cuda_bf16.h>
#include <cstdint>

#define LATENT 64
#define OUT    128
#define H      32
#define BM     128
#define PITCH  144   // bytes per smem tile row (72 bf16) — conflict-free ldmatrix

// smem layout (dynamic)
#define SM_SP   0
#define SM_SN   512
#define SM_B3   1024
#define SM_AHI  1536
#define SM_ALO  (SM_AHI + BM * PITCH)     // 19968
#define SM_BHI  (SM_ALO + BM * PITCH)     // 38400
#define SM_BLO  (SM_BHI + OUT * PITCH)    // 56832
#define SM_TOTAL (SM_BLO + OUT * PITCH)   // 75264

// Scratch (no device allocation allowed)
__device__ float g_sp[OUT];
__device__ float g_sn[OUT];
__device__ int   g_slow = 0;
__device__ __align__(16) unsigned short g_bhi[OUT * LATENT];
__device__ __align__(16) unsigned short g_blo[OUT * LATENT];

// ---------------------------------------------------------------------------
// PTX helpers (family-portable only: ldmatrix + mma.sync + cp.async)
// ---------------------------------------------------------------------------
__device__ __forceinline__ uint32_t smem_u32(const void* p) {
    uint32_t a;
    asm("{ .reg .u64 t; cvta.to.shared.u64 t, %1; cvt.u32.u64 %0, t; }"
        : "=r"(a) : "l"(p));
    return a;
}
#define LDSM_X4(r0, r1, r2, r3, addr)                                          \
    asm volatile("ldmatrix.sync.aligned.m8n8.x4.shared.b16 {%0,%1,%2,%3}, [%4];" \
                 : "=r"(r0), "=r"(r1), "=r"(r2), "=r"(r3) : "r"(addr))
#define LDSM_X2(r0, r1, addr)                                                  \
    asm volatile("ldmatrix.sync.aligned.m8n8.x2.shared.b16 {%0,%1}, [%2];"     \
                 : "=r"(r0), "=r"(r1) : "r"(addr))
#define MMA_BF16(c, a, b)                                                      \
    asm volatile("mma.sync.aligned.m16n8k16.row.col.f32.bf16.bf16.f32 "        \
                 "{%0,%1,%2,%3},{%4,%5,%6,%7},{%8,%9},{%0,%1,%2,%3};"          \
                 : "+f"((c)[0]), "+f"((c)[1]), "+f"((c)[2]), "+f"((c)[3])      \
                 : "r"((a)[0]), "r"((a)[1]), "r"((a)[2]), "r"((a)[3]),         \
                   "r"((b)[0]), "r"((b)[1]))
#define CP_ASYNC16(smem_addr, gptr)                                            \
    asm volatile("cp.async.ca.shared.global [%0], [%1], 16;"                   \
                 :: "r"(smem_addr), "l"(gptr))

__device__ __forceinline__ unsigned pack_bf16(float a, float b) {
    __nv_bfloat162 t = __floats2bfloat162_rn(a, b);
    return *(unsigned*)&t;
}
// hi halves of two fp32 -> packed bf16x2 (truncation split), 1 PRMT
__device__ __forceinline__ unsigned prmt_hi(unsigned u0, unsigned u1) {
    unsigned r;
    asm("prmt.b32 %0, %1, %2, 0x7632;" : "=r"(r) : "r"(u0), "r"(u1));
    return r;
}

// ---------------------------------------------------------------------------
// Precompute: collapsed slopes sp/sn (valid when b1==b2==0; sets g_slow
// otherwise) AND the bf16 hi/lo split of |Wp| into g_bhi/g_blo.
// One warp per feature d.
// ---------------------------------------------------------------------------
__global__ void precompute_kernel(const float* __restrict__ Wp,
                                  const float* __restrict__ W1,
                                  const float* __restrict__ b1,
                                  const float* __restrict__ W2,
                                  const float* __restrict__ b2,
                                  const float* __restrict__ W3)
{
    const int d    = blockIdx.x;
    const int lane = threadIdx.x;

#pragma unroll
    for (int j = 0; j < 2; ++j) {
        int k = lane * 2 + j;
        float w = fabsf(Wp[d * LATENT + k]);
        __nv_bfloat16 hi = __float2bfloat16_rn(w);
        float lo = w - __bfloat162float(hi);
        g_bhi[d * LATENT + k] = __bfloat16_as_ushort(hi);
        g_blo[d * LATENT + k] = __bfloat16_as_ushort(__float2bfloat16_rn(lo));
    }

    float w1v = W1[d * H + lane];
    int   nz  = (b1[d * H + lane] != 0.f) | (b2[d * H + lane] != 0.f);

    const float4* w2 = (const float4*)(W2 + ((long)d * H + lane) * H);
    float up = 0.f, un = 0.f;
#pragma unroll
    for (int q = 0; q < H / 4; ++q) {
        float4 w = w2[q];
        float wv[4] = {w.x, w.y, w.z, w.w};
#pragma unroll
        for (int j = 0; j < 4; ++j) {
            float w1h = __shfl_sync(0xffffffffu, w1v, q * 4 + j);
            up = fmaf(wv[j], fmaxf(w1h, 0.f), up);
            un = fmaf(wv[j], fmaxf(-w1h, 0.f), un);
        }
    }
    float w3 = W3[d * H + lane];
    float tp = w3 * fmaxf(up, 0.f);
    float tn = w3 * fmaxf(un, 0.f);
#pragma unroll
    for (int off = 16; off > 0; off >>= 1) {
        tp += __shfl_down_sync(0xffffffffu, tp, off);
        tn += __shfl_down_sync(0xffffffffu, tn, off);
    }
    unsigned any_nz = __ballot_sync(0xffffffffu, nz);
    if (lane == 0) {
        g_sp[d] = tp;
        g_sn[d] = tn;
        if (any_nz) atomicOr(&g_slow, 1);
    }
}

// ---------------------------------------------------------------------------
// Main: bf16x3 mma.sync GEMM (BM=128 x 128, K=64) + fused epilogue.
// Fallback (full per-element MLP) is merged: taken only if g_slow.
// ---------------------------------------------------------------------------
__global__ __launch_bounds__(256, 2) void main_kernel(
    const float* __restrict__ z,  const float* __restrict__ Wp,
    const float* __restrict__ W1, const float* __restrict__ b1,
    const float* __restrict__ W2, const float* __restrict__ b2,
    const float* __restrict__ W3, const float* __restrict__ b3,
    float* __restrict__ out, long total)
{
    if (g_slow) {   // exact fallback path (never taken when b1==b2==0)
        for (long idx = (long)blockIdx.x * blockDim.x + threadIdx.x; idx < total;
             idx += (long)gridDim.x * blockDim.x) {
            int n = (int)(idx >> 7);
            int d = (int)(idx & (OUT - 1));
            float y = 0.f;
#pragma unroll
            for (int k = 0; k < LATENT; ++k)
                y = fmaf(z[(long)n * LATENT + k], fabsf(Wp[d * LATENT + k]), y);
            float h1[H];
#pragma unroll
            for (int h = 0; h < H; ++h)
                h1[h] = fmaxf(fmaf(y, W1[d * H + h], b1[d * H + h]), 0.f);
            float x = b3[d];
#pragma unroll 4
            for (int k = 0; k < H; ++k) {
                float t = b2[d * H + k];
                const float* w2 = W2 + ((long)d * H + k) * H;
#pragma unroll
                for (int h = 0; h < H; ++h) t = fmaf(w2[h], h1[h], t);
                x = fmaf(W3[d * H + k], fmaxf(t, 0.f), x);
            }
            out[idx] = fabsf(x);
        }
        return;
    }

    extern __shared__ char smem[];
    const uint32_t sb = smem_u32(smem);
    const int tid  = threadIdx.x;
    const int wid  = tid >> 5;
    const int lane = tid & 31;
    const int wm   = wid >> 2;   // 0..1 -> rows wm*64
    const int wn   = wid & 3;    // 0..3 -> cols wn*32
    const int brow = blockIdx.x * BM;

    // B hi/lo via cp.async (precomputed |Wp| split, L2-hot): 2048 x 16B
    {
#pragma unroll
        for (int i = 0; i < 4; ++i) {
            int idx = tid + i * 256;        // 1024 uint4 per tile
            int row = idx >> 3;
            int seg = idx & 7;
            uint32_t off = (uint32_t)(row * PITCH + seg * 16);
            CP_ASYNC16(sb + SM_BHI + off, (const char*)g_bhi + idx * 16);
            CP_ASYNC16(sb + SM_BLO + off, (const char*)g_blo + idx * 16);
        }
        asm volatile("cp.async.commit_group;" ::: "memory");
    }

    // Stage epilogue constants
    if (tid < OUT) {
        ((float*)(smem + SM_SP))[tid] = g_sp[tid];
        ((float*)(smem + SM_SN))[tid] = g_sn[tid];
        ((float*)(smem + SM_B3))[tid] = b3[tid];
    }

    // Load z tile (128 x 64 fp32, streaming), truncation-split to bf16 hi/lo.
    {
        const int row  = tid >> 1;
        const int half = tid & 1;
        const float4* zr = (const float4*)(z + (size_t)(brow + row) * LATENT + half * 32);
        float4 v[8];
#pragma unroll
        for (int j = 0; j < 8; ++j) v[j] = __ldcs(zr + j);   // MLP=8 up front
#pragma unroll
        for (int j = 0; j < 4; ++j) {
            float f[8] = {v[j*2].x, v[j*2].y, v[j*2].z, v[j*2].w,
                          v[j*2+1].x, v[j*2+1].y, v[j*2+1].z, v[j*2+1].w};
            uint4 uh;
            uh.x = prmt_hi(__float_as_uint(f[0]), __float_as_uint(f[1]));
            uh.y = prmt_hi(__float_as_uint(f[2]), __float_as_uint(f[3]));
            uh.z = prmt_hi(__float_as_uint(f[4]), __float_as_uint(f[5]));
            uh.w = prmt_hi(__float_as_uint(f[6]), __float_as_uint(f[7]));
            float lo[8];
#pragma unroll
            for (int e = 0; e < 8; ++e) {
                float hi = __uint_as_float(__float_as_uint(f[e]) & 0xFFFF0000u);
                lo[e] = f[e] - hi;          // exact
            }
            uint4 ul;
            ul.x = pack_bf16(lo[0], lo[1]); ul.y = pack_bf16(lo[2], lo[3]);
            ul.z = pack_bf16(lo[4], lo[5]); ul.w = pack_bf16(lo[6], lo[7]);
            int off = row * PITCH + (half * 32 + j * 8) * 2;
            *(uint4*)(smem + SM_AHI + off) = uh;
            *(uint4*)(smem + SM_ALO + off) = ul;
        }
    }

    asm volatile("cp.async.wait_group 0;" ::: "memory");
    __syncthreads();

    // ldmatrix lane base addresses
    const uint32_t aoff = sb + (uint32_t)((wm * 64 + (lane & 15)) * PITCH +
                                          ((lane >> 4) * 8) * 2);
    const uint32_t boff = sb + (uint32_t)((wn * 32 + (lane & 7)) * PITCH +
                                          (((lane >> 3) & 1) * 8) * 2);

    float acc[4][4][4];
#pragma unroll
    for (int f = 0; f < 4; ++f)
#pragma unroll
        for (int g = 0; g < 4; ++g)
#pragma unroll
            for (int e = 0; e < 4; ++e) acc[f][g][e] = 0.f;

    // K=64 in 4 k16 steps; per step: A frags loaded once, b_hi reused twice.
#pragma unroll
    for (int s = 0; s < 4; ++s) {
        uint32_t ah[4][4], al[4][4], bh[4][2], bl[4][2];
#pragma unroll
        for (int f = 0; f < 4; ++f)
            LDSM_X4(ah[f][0], ah[f][1], ah[f][2], ah[f][3],
                    aoff + SM_AHI + f * 16 * PITCH + s * 32);
#pragma unroll
        for (int g = 0; g < 4; ++g)
            LDSM_X2(bh[g][0], bh[g][1], boff + SM_BHI + g * 8 * PITCH + s * 32);
#pragma unroll
        for (int f = 0; f < 4; ++f)
            LDSM_X4(al[f][0], al[f][1], al[f][2], al[f][3],
                    aoff + SM_ALO + f * 16 * PITCH + s * 32);
#pragma unroll
        for (int f = 0; f < 4; ++f)
#pragma unroll
            for (int g = 0; g < 4; ++g)
                MMA_BF16(acc[f][g], ah[f], bh[g]);
#pragma unroll
        for (int g = 0; g < 4; ++g)
            LDSM_X2(bl[g][0], bl[g][1], boff + SM_BLO + g * 8 * PITCH + s * 32);
#pragma unroll
        for (int f = 0; f < 4; ++f)
#pragma unroll
            for (int g = 0; g < 4; ++g)
                MMA_BF16(acc[f][g], al[f], bh[g]);
#pragma unroll
        for (int f = 0; f < 4; ++f)
#pragma unroll
            for (int g = 0; g < 4; ++g)
                MMA_BF16(acc[f][g], ah[f], bl[g]);
    }

    // Fused epilogue straight from fragments (streaming stores).
    {
        const int qrow = lane >> 2;
        const int qcol = 2 * (lane & 3);
        const float* sps = (const float*)(smem + SM_SP);
        const float* sns = (const float*)(smem + SM_SN);
        const float* b3s = (const float*)(smem + SM_B3);
#pragma unroll
        for (int g = 0; g < 4; ++g) {
            const int c0 = wn * 32 + g * 8 + qcol;
            float sp0 = sps[c0], sp1 = sps[c0 + 1];
            float sn0 = sns[c0], sn1 = sns[c0 + 1];
            float t0  = b3s[c0], t1  = b3s[c0 + 1];
#pragma unroll
            for (int f = 0; f < 4; ++f) {
                const int r0 = brow + wm * 64 + f * 16 + qrow;
                float y0 = acc[f][g][0], y1 = acc[f][g][1];
                float y2 = acc[f][g][2], y3 = acc[f][g][3];
                float o0 = fabsf(fmaf(fabsf(y0), (y0 > 0.f ? sp0 : sn0), t0));
                float o1 = fabsf(fmaf(fabsf(y1), (y1 > 0.f ? sp1 : sn1), t1));
                float o2 = fabsf(fmaf(fabsf(y2), (y2 > 0.f ? sp0 : sn0), t0));
                float o3 = fabsf(fmaf(fabsf(y3), (y3 > 0.f ? sp1 : sn1), t1));
                __stcs((float2*)(out + (size_t)r0 * OUT + c0),       make_float2(o0, o1));
                __stcs((float2*)(out + (size_t)(r0 + 8) * OUT + c0), make_float2(o2, o3));
            }
        }
    }
}

// ---------------------------------------------------------------------------
extern "C" void kernel_launch(void* const* d_in, const int* in_sizes, int n_in,
                              void* d_out, int out_size)
{
    const float* z  = (const float*)d_in[0];
    const float* Wp = (const float*)d_in[1];
    const float* W1 = (const float*)d_in[2];
    const float* b1 = (const float*)d_in[3];
    const float* W2 = (const float*)d_in[4];
    const float* b2 = (const float*)d_in[5];
    const float* W3 = (const float*)d_in[6];
    const float* b3 = (const float*)d_in[7];
    float* out = (float*)d_out;

    int nrows = in_sizes[0] / LATENT;   // 65536

    cudaFuncSetAttribute(main_kernel,
                         cudaFuncAttributeMaxDynamicSharedMemorySize, SM_TOTAL);

    precompute_kernel<<<OUT, 32>>>(Wp, W1, b1, W2, b2, W3);
    main_kernel<<<nrows / BM, 256, SM_TOTAL>>>(z, Wp, W1, b1, W2, b2, W3, b3,
                                               out, (long)nrows * OUT);
}

// round 6
// speedup vs baseline: 5.5181x; 1.0843x over previous
#include <cuda_runtime.h>
#include <cuda_bf16.h>
#include <cstdint>

#define LATENT 64
#define OUT    128
#define H      32
#define BM     64    // rows per CTA
#define PITCH  144   // bytes per smem tile row (72 bf16) — conflict-free ldmatrix

// smem layout (dynamic)
#define SM_SP   0
#define SM_SN   512
#define SM_B3   1024
#define SM_AHI  1536
#define SM_ALO  (SM_AHI + BM * PITCH)     // 10752
#define SM_BHI  (SM_ALO + BM * PITCH)     // 19968
#define SM_BLO  (SM_BHI + OUT * PITCH)    // 38400
#define SM_TOTAL (SM_BLO + OUT * PITCH)   // 56832  (3 CTAs/SM)

// Scratch (no device allocation allowed)
__device__ float g_sp[OUT];
__device__ float g_sn[OUT];
__device__ int   g_slow = 0;
__device__ __align__(16) unsigned short g_bhi[OUT * LATENT];
__device__ __align__(16) unsigned short g_blo[OUT * LATENT];

// ---------------------------------------------------------------------------
// PTX helpers (family-portable only: ldmatrix + mma.sync + cp.async)
// ---------------------------------------------------------------------------
__device__ __forceinline__ uint32_t smem_u32(const void* p) {
    uint32_t a;
    asm("{ .reg .u64 t; cvta.to.shared.u64 t, %1; cvt.u32.u64 %0, t; }"
        : "=r"(a) : "l"(p));
    return a;
}
#define LDSM_X4(r0, r1, r2, r3, addr)                                          \
    asm volatile("ldmatrix.sync.aligned.m8n8.x4.shared.b16 {%0,%1,%2,%3}, [%4];" \
                 : "=r"(r0), "=r"(r1), "=r"(r2), "=r"(r3) : "r"(addr))
#define LDSM_X2(r0, r1, addr)                                                  \
    asm volatile("ldmatrix.sync.aligned.m8n8.x2.shared.b16 {%0,%1}, [%2];"     \
                 : "=r"(r0), "=r"(r1) : "r"(addr))
#define MMA_BF16(c, a, b)                                                      \
    asm volatile("mma.sync.aligned.m16n8k16.row.col.f32.bf16.bf16.f32 "        \
                 "{%0,%1,%2,%3},{%4,%5,%6,%7},{%8,%9},{%0,%1,%2,%3};"          \
                 : "+f"((c)[0]), "+f"((c)[1]), "+f"((c)[2]), "+f"((c)[3])      \
                 : "r"((a)[0]), "r"((a)[1]), "r"((a)[2]), "r"((a)[3]),         \
                   "r"((b)[0]), "r"((b)[1]))
#define CP_ASYNC16(smem_addr, gptr)                                            \
    asm volatile("cp.async.ca.shared.global [%0], [%1], 16;"                   \
                 :: "r"(smem_addr), "l"(gptr))

__device__ __forceinline__ unsigned pack_bf16(float a, float b) {
    __nv_bfloat162 t = __floats2bfloat162_rn(a, b);
    return *(unsigned*)&t;
}
// hi halves of two fp32 -> packed bf16x2 (truncation split), 1 PRMT
__device__ __forceinline__ unsigned prmt_hi(unsigned u0, unsigned u1) {
    unsigned r;
    asm("prmt.b32 %0, %1, %2, 0x7632;" : "=r"(r) : "r"(u0), "r"(u1));
    return r;
}

// ---------------------------------------------------------------------------
// Precompute: collapsed slopes sp/sn (valid when b1==b2==0; sets g_slow
// otherwise) AND the bf16 hi/lo split of |Wp| into g_bhi/g_blo.
// One warp per feature d. All global loads issued before dependent math.
// ---------------------------------------------------------------------------
__global__ void precompute_kernel(const float* __restrict__ Wp,
                                  const float* __restrict__ W1,
                                  const float* __restrict__ b1,
                                  const float* __restrict__ W2,
                                  const float* __restrict__ b2,
                                  const float* __restrict__ W3)
{
    const int d    = blockIdx.x;
    const int lane = threadIdx.x;

    // Issue every load up front (MLP ~13)
    float2 wp2 = *(const float2*)(Wp + d * LATENT + lane * 2);
    float  w1v = W1[d * H + lane];
    float  b1v = b1[d * H + lane];
    float  b2v = b2[d * H + lane];
    float  w3  = W3[d * H + lane];
    const float4* w2 = (const float4*)(W2 + ((long)d * H + lane) * H);
    float4 w2v[8];
#pragma unroll
    for (int q = 0; q < H / 4; ++q) w2v[q] = w2[q];

    // |Wp| bf16 hi/lo split
    {
        float wa = fabsf(wp2.x), wb = fabsf(wp2.y);
        __nv_bfloat16 ha = __float2bfloat16_rn(wa);
        __nv_bfloat16 hb = __float2bfloat16_rn(wb);
        g_bhi[d * LATENT + lane * 2]     = __bfloat16_as_ushort(ha);
        g_bhi[d * LATENT + lane * 2 + 1] = __bfloat16_as_ushort(hb);
        g_blo[d * LATENT + lane * 2]     =
            __bfloat16_as_ushort(__float2bfloat16_rn(wa - __bfloat162float(ha)));
        g_blo[d * LATENT + lane * 2 + 1] =
            __bfloat16_as_ushort(__float2bfloat16_rn(wb - __bfloat162float(hb)));
    }

    int nz = (b1v != 0.f) | (b2v != 0.f);

    float up = 0.f, un = 0.f;
#pragma unroll
    for (int q = 0; q < H / 4; ++q) {
        float wv[4] = {w2v[q].x, w2v[q].y, w2v[q].z, w2v[q].w};
#pragma unroll
        for (int j = 0; j < 4; ++j) {
            float w1h = __shfl_sync(0xffffffffu, w1v, q * 4 + j);
            up = fmaf(wv[j], fmaxf(w1h, 0.f), up);
            un = fmaf(wv[j], fmaxf(-w1h, 0.f), un);
        }
    }
    float tp = w3 * fmaxf(up, 0.f);
    float tn = w3 * fmaxf(un, 0.f);
#pragma unroll
    for (int off = 16; off > 0; off >>= 1) {
        tp += __shfl_down_sync(0xffffffffu, tp, off);
        tn += __shfl_down_sync(0xffffffffu, tn, off);
    }
    unsigned any_nz = __ballot_sync(0xffffffffu, nz);
    if (lane == 0) {
        g_sp[d] = tp;
        g_sn[d] = tn;
        if (any_nz) atomicOr(&g_slow, 1);
    }
}

// ---------------------------------------------------------------------------
// Main: bf16x3 mma.sync GEMM (BM=64 x 128, K=64) + fused epilogue.
// 8 warps, warp tile 32(m) x 32(n). 3 CTAs/SM for phase overlap.
// Fallback (full per-element MLP) is merged: taken only if g_slow.
// ---------------------------------------------------------------------------
__global__ __launch_bounds__(256, 3) void main_kernel(
    const float* __restrict__ z,  const float* __restrict__ Wp,
    const float* __restrict__ W1, const float* __restrict__ b1,
    const float* __restrict__ W2, const float* __restrict__ b2,
    const float* __restrict__ W3, const float* __restrict__ b3,
    float* __restrict__ out, long total)
{
    if (g_slow) {   // exact fallback path (never taken when b1==b2==0)
        for (long idx = (long)blockIdx.x * blockDim.x + threadIdx.x; idx < total;
             idx += (long)gridDim.x * blockDim.x) {
            int n = (int)(idx >> 7);
            int d = (int)(idx & (OUT - 1));
            float y = 0.f;
#pragma unroll
            for (int k = 0; k < LATENT; ++k)
                y = fmaf(z[(long)n * LATENT + k], fabsf(Wp[d * LATENT + k]), y);
            float h1[H];
#pragma unroll
            for (int h = 0; h < H; ++h)
                h1[h] = fmaxf(fmaf(y, W1[d * H + h], b1[d * H + h]), 0.f);
            float x = b3[d];
#pragma unroll 4
            for (int k = 0; k < H; ++k) {
                float t = b2[d * H + k];
                const float* w2 = W2 + ((long)d * H + k) * H;
#pragma unroll
                for (int h = 0; h < H; ++h) t = fmaf(w2[h], h1[h], t);
                x = fmaf(W3[d * H + k], fmaxf(t, 0.f), x);
            }
            out[idx] = fabsf(x);
        }
        return;
    }

    extern __shared__ char smem[];
    const uint32_t sb = smem_u32(smem);
    const int tid  = threadIdx.x;
    const int wid  = tid >> 5;
    const int lane = tid & 31;
    const int wm   = wid >> 2;   // 0..1 -> rows wm*32
    const int wn   = wid & 3;    // 0..3 -> cols wn*32
    const int brow = blockIdx.x * BM;

    // z tile loads issued first (deepest latency): 64 rows x 64 f32.
    // Thread: row = tid>>2, seg = tid&3 -> 16 consecutive floats.
    const int zrow = tid >> 2;
    const int zseg = tid & 3;
    const float4* zr = (const float4*)(z + (size_t)(brow + zrow) * LATENT + zseg * 16);
    float4 v[4];
#pragma unroll
    for (int j = 0; j < 4; ++j) v[j] = __ldcs(zr + j);

    // B hi/lo via cp.async (precomputed |Wp| split, L2-hot): 2048 x 16B
#pragma unroll
    for (int i = 0; i < 4; ++i) {
        int idx = tid + i * 256;        // 1024 uint4 per tile
        int row = idx >> 3;
        int seg = idx & 7;
        uint32_t off = (uint32_t)(row * PITCH + seg * 16);
        CP_ASYNC16(sb + SM_BHI + off, (const char*)g_bhi + idx * 16);
        CP_ASYNC16(sb + SM_BLO + off, (const char*)g_blo + idx * 16);
    }
    asm volatile("cp.async.commit_group;" ::: "memory");

    // Stage epilogue constants
    if (tid < OUT) {
        ((float*)(smem + SM_SP))[tid] = g_sp[tid];
        ((float*)(smem + SM_SN))[tid] = g_sn[tid];
        ((float*)(smem + SM_B3))[tid] = b3[tid];
    }

    // Truncation-split z to bf16 hi/lo and store to smem
#pragma unroll
    for (int grp = 0; grp < 2; ++grp) {
        float f[8] = {v[grp*2].x, v[grp*2].y, v[grp*2].z, v[grp*2].w,
                      v[grp*2+1].x, v[grp*2+1].y, v[grp*2+1].z, v[grp*2+1].w};
        uint4 uh;
        uh.x = prmt_hi(__float_as_uint(f[0]), __float_as_uint(f[1]));
        uh.y = prmt_hi(__float_as_uint(f[2]), __float_as_uint(f[3]));
        uh.z = prmt_hi(__float_as_uint(f[4]), __float_as_uint(f[5]));
        uh.w = prmt_hi(__float_as_uint(f[6]), __float_as_uint(f[7]));
        float lo[8];
#pragma unroll
        for (int e = 0; e < 8; ++e) {
            float hi = __uint_as_float(__float_as_uint(f[e]) & 0xFFFF0000u);
            lo[e] = f[e] - hi;          // exact
        }
        uint4 ul;
        ul.x = pack_bf16(lo[0], lo[1]); ul.y = pack_bf16(lo[2], lo[3]);
        ul.z = pack_bf16(lo[4], lo[5]); ul.w = pack_bf16(lo[6], lo[7]);
        int off = zrow * PITCH + (zseg * 16 + grp * 8) * 2;
        *(uint4*)(smem + SM_AHI + off) = uh;
        *(uint4*)(smem + SM_ALO + off) = ul;
    }

    asm volatile("cp.async.wait_group 0;" ::: "memory");
    __syncthreads();

    // ldmatrix lane base addresses
    const uint32_t aoff = sb + (uint32_t)((wm * 32 + (lane & 15)) * PITCH +
                                          (lane >> 4) * 16);
    const uint32_t boff = sb + (uint32_t)((wn * 32 + (lane & 7)) * PITCH +
                                          ((lane >> 3) & 1) * 16);

    float acc[2][4][4];
#pragma unroll
    for (int f = 0; f < 2; ++f)
#pragma unroll
        for (int g = 0; g < 4; ++g)
#pragma unroll
            for (int e = 0; e < 4; ++e) acc[f][g][e] = 0.f;

    // K=64 in 4 k16 steps; per step: A frags loaded once, b_hi reused twice.
#pragma unroll
    for (int s = 0; s < 4; ++s) {
        uint32_t ah[2][4], al[2][4], bh[4][2], bl[4][2];
#pragma unroll
        for (int f = 0; f < 2; ++f)
            LDSM_X4(ah[f][0], ah[f][1], ah[f][2], ah[f][3],
                    aoff + SM_AHI + f * 16 * PITCH + s * 32);
#pragma unroll
        for (int g = 0; g < 4; ++g)
            LDSM_X2(bh[g][0], bh[g][1], boff + SM_BHI + g * 8 * PITCH + s * 32);
#pragma unroll
        for (int f = 0; f < 2; ++f)
            LDSM_X4(al[f][0], al[f][1], al[f][2], al[f][3],
                    aoff + SM_ALO + f * 16 * PITCH + s * 32);
#pragma unroll
        for (int f = 0; f < 2; ++f)
#pragma unroll
            for (int g = 0; g < 4; ++g)
                MMA_BF16(acc[f][g], ah[f], bh[g]);
#pragma unroll
        for (int g = 0; g < 4; ++g)
            LDSM_X2(bl[g][0], bl[g][1], boff + SM_BLO + g * 8 * PITCH + s * 32);
#pragma unroll
        for (int f = 0; f < 2; ++f)
#pragma unroll
            for (int g = 0; g < 4; ++g)
                MMA_BF16(acc[f][g], al[f], bh[g]);
#pragma unroll
        for (int f = 0; f < 2; ++f)
#pragma unroll
            for (int g = 0; g < 4; ++g)
                MMA_BF16(acc[f][g], ah[f], bl[g]);
    }

    // Fused epilogue straight from fragments (streaming stores).
    {
        const int qrow = lane >> 2;
        const int qcol = 2 * (lane & 3);
        const float* sps = (const float*)(smem + SM_SP);
        const float* sns = (const float*)(smem + SM_SN);
        const float* b3s = (const float*)(smem + SM_B3);
#pragma unroll
        for (int g = 0; g < 4; ++g) {
            const int c0 = wn * 32 + g * 8 + qcol;
            float sp0 = sps[c0], sp1 = sps[c0 + 1];
            float sn0 = sns[c0], sn1 = sns[c0 + 1];
            float t0  = b3s[c0], t1  = b3s[c0 + 1];
#pragma unroll
            for (int f = 0; f < 2; ++f) {
                const int r0 = brow + wm * 32 + f * 16 + qrow;
                float y0 = acc[f][g][0], y1 = acc[f][g][1];
                float y2 = acc[f][g][2], y3 = acc[f][g][3];
                float o0 = fabsf(fmaf(fabsf(y0), (y0 > 0.f ? sp0 : sn0), t0));
                float o1 = fabsf(fmaf(fabsf(y1), (y1 > 0.f ? sp1 : sn1), t1));
                float o2 = fabsf(fmaf(fabsf(y2), (y2 > 0.f ? sp0 : sn0), t0));
                float o3 = fabsf(fmaf(fabsf(y3), (y3 > 0.f ? sp1 : sn1), t1));
                __stcs((float2*)(out + (size_t)r0 * OUT + c0),       make_float2(o0, o1));
                __stcs((float2*)(out + (size_t)(r0 + 8) * OUT + c0), make_float2(o2, o3));
            }
        }
    }
}

// ---------------------------------------------------------------------------
extern "C" void kernel_launch(void* const* d_in, const int* in_sizes, int n_in,
                              void* d_out, int out_size)
{
    const float* z  = (const float*)d_in[0];
    const float* Wp = (const float*)d_in[1];
    const float* W1 = (const float*)d_in[2];
    const float* b1 = (const float*)d_in[3];
    const float* W2 = (const float*)d_in[4];
    const float* b2 = (const float*)d_in[5];
    const float* W3 = (const float*)d_in[6];
    const float* b3 = (const float*)d_in[7];
    float* out = (float*)d_out;

    int nrows = in_sizes[0] / LATENT;   // 65536

    cudaFuncSetAttribute(main_kernel,
                         cudaFuncAttributeMaxDynamicSharedMemorySize, SM_TOTAL);

    precompute_kernel<<<OUT, 32>>>(Wp, W1, b1, W2, b2, W3);
    main_kernel<<<nrows / BM, 256, SM_TOTAL>>>(z, Wp, W1, b1, W2, b2, W3, b3,
                                               out, (long)nrows * OUT);
}

// round 8
// speedup vs baseline: 6.1892x; 1.1216x over previous
#include <cuda_runtime.h>
#include <cuda_fp16.h>
#include <cstdint>

#define LATENT 64
#define OUT    128
#define H      32
#define BM     64    // rows per CTA
#define PITCH  144   // bytes per smem A row (72 fp16) — conflict-free ldmatrix

// smem layout (dynamic)
#define SM_SP   0
#define SM_SN   512
#define SM_B3   1024
#define SM_AHI  1536
#define SM_ALO  (SM_AHI + BM * PITCH)     // 10752
#define SM_TOTAL (SM_ALO + BM * PITCH)    // 19968

// Scratch (no device allocation allowed)
__device__ float g_sp[OUT];
__device__ float g_sn[OUT];
__device__ int   g_slow = 0;
// B mma fragments, fp16, exact mma B-operand lane layout:
// u32 index = (((wn*4+g)*4+s)*32 + lane)*2 + reg
//   strides (u32): wn:1024, g:256, s:64, lane:2
__device__ __align__(16) uint32_t g_bf[4 * 4 * 4 * 32 * 2];

// ---------------------------------------------------------------------------
// PTX helpers (family-portable only: ldmatrix + mma.sync)
// ---------------------------------------------------------------------------
__device__ __forceinline__ uint32_t smem_u32(const void* p) {
    uint32_t a;
    asm("{ .reg .u64 t; cvta.to.shared.u64 t, %1; cvt.u32.u64 %0, t; }"
        : "=r"(a) : "l"(p));
    return a;
}
#define LDSM_X4(r0, r1, r2, r3, addr)                                          \
    asm volatile("ldmatrix.sync.aligned.m8n8.x4.shared.b16 {%0,%1,%2,%3}, [%4];" \
                 : "=r"(r0), "=r"(r1), "=r"(r2), "=r"(r3) : "r"(addr))
#define MMA_F16(c, a, b)                                                       \
    asm volatile("mma.sync.aligned.m16n8k16.row.col.f32.f16.f16.f32 "          \
                 "{%0,%1,%2,%3},{%4,%5,%6,%7},{%8,%9},{%0,%1,%2,%3};"          \
                 : "+f"((c)[0]), "+f"((c)[1]), "+f"((c)[2]), "+f"((c)[3])      \
                 : "r"((a)[0]), "r"((a)[1]), "r"((a)[2]), "r"((a)[3]),         \
                   "r"((b)[0]), "r"((b)[1]))

__device__ __forceinline__ uint32_t pack_h2(float a, float b) {
    __half2 h = __floats2half2_rn(a, b);
    return *(uint32_t*)&h;
}

// ---------------------------------------------------------------------------
// Precompute (one block per feature d, 32 lanes):
//  - collapsed slopes sp/sn (valid when b1==b2==0; sets g_slow otherwise)
//  - fp16 B fragments of |Wp| in exact mma B lane layout (lanes 0-15)
// ---------------------------------------------------------------------------
__global__ void precompute_kernel(const float* __restrict__ Wp,
                                  const float* __restrict__ W1,
                                  const float* __restrict__ b1,
                                  const float* __restrict__ W2,
                                  const float* __restrict__ b2,
                                  const float* __restrict__ W3)
{
    const int d    = blockIdx.x;
    const int lane = threadIdx.x;

    // Issue all loads up front
    float  w1v = W1[d * H + lane];
    float  b1v = b1[d * H + lane];
    float  b2v = b2[d * H + lane];
    float  w3  = W3[d * H + lane];
    const float4* w2 = (const float4*)(W2 + ((long)d * H + lane) * H);
    float4 w2v[8];
#pragma unroll
    for (int q = 0; q < H / 4; ++q) w2v[q] = w2[q];

    // B fragments: lanes 0-15 -> (s = lane>>2, kq = lane&3)
    // mma m16n8k16 B operand: lane L holds b[k][n] with n = L/4,
    // reg0: k = (L%4)*2 + {0,1}; reg1: k = 8 + (L%4)*2 + {0,1}
    if (lane < 16) {
        const int s  = lane >> 2;
        const int kq = lane & 3;
        const int k0 = s * 16 + kq * 2;
        float f0 = fabsf(Wp[d * LATENT + k0]);
        float f1 = fabsf(Wp[d * LATENT + k0 + 1]);
        float f2 = fabsf(Wp[d * LATENT + k0 + 8]);
        float f3 = fabsf(Wp[d * LATENT + k0 + 9]);
        const int wn    = d >> 5;
        const int g     = (d >> 3) & 3;
        const int flane = (d & 7) * 4 + kq;
        const int idx   = ((((wn * 4 + g) * 4 + s) * 32) + flane) * 2;
        g_bf[idx]     = pack_h2(f0, f1);
        g_bf[idx + 1] = pack_h2(f2, f3);
    }

    int nz = (b1v != 0.f) | (b2v != 0.f);

    float up = 0.f, un = 0.f;
#pragma unroll
    for (int q = 0; q < H / 4; ++q) {
        float wv[4] = {w2v[q].x, w2v[q].y, w2v[q].z, w2v[q].w};
#pragma unroll
        for (int j = 0; j < 4; ++j) {
            float w1h = __shfl_sync(0xffffffffu, w1v, q * 4 + j);
            up = fmaf(wv[j], fmaxf(w1h, 0.f), up);
            un = fmaf(wv[j], fmaxf(-w1h, 0.f), un);
        }
    }
    float tp = w3 * fmaxf(up, 0.f);
    float tn = w3 * fmaxf(un, 0.f);
#pragma unroll
    for (int off = 16; off > 0; off >>= 1) {
        tp += __shfl_down_sync(0xffffffffu, tp, off);
        tn += __shfl_down_sync(0xffffffffu, tn, off);
    }
    unsigned any_nz = __ballot_sync(0xffffffffu, nz);
    if (lane == 0) {
        g_sp[d] = tp;
        g_sn[d] = tn;
        if (any_nz) atomicOr(&g_slow, 1);
    }
}

// ---------------------------------------------------------------------------
// Main: fp16 2-term mma.sync GEMM (BM=64 x 128, K=64) + fused epilogue.
// A = a_hi + a_lo (fp16 split, smem+ldmatrix); B = fp16 fragments from gmem.
// 8 warps, warp tile 32(m) x 32(n), 3 CTAs/SM.
// ---------------------------------------------------------------------------
__global__ __launch_bounds__(256, 3) void main_kernel(
    const float* __restrict__ z,  const float* __restrict__ Wp,
    const float* __restrict__ W1, const float* __restrict__ b1,
    const float* __restrict__ W2, const float* __restrict__ b2,
    const float* __restrict__ W3, const float* __restrict__ b3,
    float* __restrict__ out, long total)
{
    if (g_slow) {   // exact fallback path (never taken when b1==b2==0)
        for (long idx = (long)blockIdx.x * blockDim.x + threadIdx.x; idx < total;
             idx += (long)gridDim.x * blockDim.x) {
            int n = (int)(idx >> 7);
            int d = (int)(idx & (OUT - 1));
            float y = 0.f;
#pragma unroll
            for (int k = 0; k < LATENT; ++k)
                y = fmaf(z[(long)n * LATENT + k], fabsf(Wp[d * LATENT + k]), y);
            float h1[H];
#pragma unroll
            for (int h = 0; h < H; ++h)
                h1[h] = fmaxf(fmaf(y, W1[d * H + h], b1[d * H + h]), 0.f);
            float x = b3[d];
#pragma unroll 4
            for (int k = 0; k < H; ++k) {
                float t = b2[d * H + k];
                const float* w2 = W2 + ((long)d * H + k) * H;
#pragma unroll
                for (int h = 0; h < H; ++h) t = fmaf(w2[h], h1[h], t);
                x = fmaf(W3[d * H + k], fmaxf(t, 0.f), x);
            }
            out[idx] = fabsf(x);
        }
        return;
    }

    extern __shared__ char smem[];
    const uint32_t sb = smem_u32(smem);
    const int tid  = threadIdx.x;
    const int wid  = tid >> 5;
    const int lane = tid & 31;
    const int wm   = wid >> 2;   // 0..1 -> rows wm*32
    const int wn   = wid & 3;    // 0..3 -> cols wn*32
    const int brow = blockIdx.x * BM;

    // z tile loads first (deepest latency): 64 rows x 64 f32.
    const int zrow = tid >> 2;
    const int zseg = tid & 3;
    const float4* zr = (const float4*)(z + (size_t)(brow + zrow) * LATENT + zseg * 16);
    float4 v[4];
#pragma unroll
    for (int j = 0; j < 4; ++j) v[j] = __ldcs(zr + j);

    // Prefetch B fragments for s=0 (gmem, L2/L1-hot).
    // Strides (u32): wn:1024, g:256, s:64, lane:2.
    const uint32_t* bfbase = g_bf + (size_t)wn * 1024 + lane * 2;
    uint32_t bcur[4][2], bnxt[4][2];
#pragma unroll
    for (int g = 0; g < 4; ++g) {
        uint2 t = *(const uint2*)(bfbase + g * 256);
        bcur[g][0] = t.x; bcur[g][1] = t.y;
    }

    // Stage epilogue constants
    if (tid < OUT) {
        ((float*)(smem + SM_SP))[tid] = g_sp[tid];
        ((float*)(smem + SM_SN))[tid] = g_sn[tid];
        ((float*)(smem + SM_B3))[tid] = b3[tid];
    }

    // fp16 hi/lo split of z into smem (hi = rn(a), lo = rn(a - hi))
#pragma unroll
    for (int grp = 0; grp < 2; ++grp) {
        float f[8] = {v[grp*2].x, v[grp*2].y, v[grp*2].z, v[grp*2].w,
                      v[grp*2+1].x, v[grp*2+1].y, v[grp*2+1].z, v[grp*2+1].w};
        uint4 uh, ul;
        uint32_t* uhp = &uh.x;
        uint32_t* ulp = &ul.x;
#pragma unroll
        for (int e = 0; e < 4; ++e) {
            __half2 h2 = __floats2half2_rn(f[e*2], f[e*2+1]);
            float2 hf = __half22float2(h2);
            uhp[e] = *(uint32_t*)&h2;
            ulp[e] = pack_h2(f[e*2] - hf.x, f[e*2+1] - hf.y);
        }
        int off = zrow * PITCH + (zseg * 16 + grp * 8) * 2;
        *(uint4*)(smem + SM_AHI + off) = uh;
        *(uint4*)(smem + SM_ALO + off) = ul;
    }
    __syncthreads();

    // ldmatrix lane base addresses (A)
    const uint32_t aoff = sb + (uint32_t)((wm * 32 + (lane & 15)) * PITCH +
                                          (lane >> 4) * 16);

    float acc[2][4][4];
#pragma unroll
    for (int f = 0; f < 2; ++f)
#pragma unroll
        for (int g = 0; g < 4; ++g)
#pragma unroll
            for (int e = 0; e < 4; ++e) acc[f][g][e] = 0.f;

    // K=64 in 4 k16 steps; B frags double-buffered from gmem.
#pragma unroll
    for (int s = 0; s < 4; ++s) {
        if (s < 3) {
#pragma unroll
            for (int g = 0; g < 4; ++g) {
                uint2 t = *(const uint2*)(bfbase + (s + 1) * 64 + g * 256);
                bnxt[g][0] = t.x; bnxt[g][1] = t.y;
            }
        }
        uint32_t ah[2][4], al[2][4];
#pragma unroll
        for (int f = 0; f < 2; ++f)
            LDSM_X4(ah[f][0], ah[f][1], ah[f][2], ah[f][3],
                    aoff + SM_AHI + f * 16 * PITCH + s * 32);
#pragma unroll
        for (int f = 0; f < 2; ++f)
            LDSM_X4(al[f][0], al[f][1], al[f][2], al[f][3],
                    aoff + SM_ALO + f * 16 * PITCH + s * 32);
#pragma unroll
        for (int f = 0; f < 2; ++f)
#pragma unroll
            for (int g = 0; g < 4; ++g)
                MMA_F16(acc[f][g], ah[f], bcur[g]);
#pragma unroll
        for (int f = 0; f < 2; ++f)
#pragma unroll
            for (int g = 0; g < 4; ++g)
                MMA_F16(acc[f][g], al[f], bcur[g]);
        if (s < 3) {
#pragma unroll
            for (int g = 0; g < 4; ++g) {
                bcur[g][0] = bnxt[g][0]; bcur[g][1] = bnxt[g][1];
            }
        }
    }

    // Fused epilogue straight from fragments (streaming stores).
    {
        const int qrow = lane >> 2;
        const int qcol = 2 * (lane & 3);
        const float* sps = (const float*)(smem + SM_SP);
        const float* sns = (const float*)(smem + SM_SN);
        const float* b3s = (const float*)(smem + SM_B3);
#pragma unroll
        for (int g = 0; g < 4; ++g) {
            const int c0 = wn * 32 + g * 8 + qcol;
            float sp0 = sps[c0], sp1 = sps[c0 + 1];
            float sn0 = sns[c0], sn1 = sns[c0 + 1];
            float t0  = b3s[c0], t1  = b3s[c0 + 1];
#pragma unroll
            for (int f = 0; f < 2; ++f) {
                const int r0 = brow + wm * 32 + f * 16 + qrow;
                float y0 = acc[f][g][0], y1 = acc[f][g][1];
                float y2 = acc[f][g][2], y3 = acc[f][g][3];
                float o0 = fabsf(fmaf(fabsf(y0), (y0 > 0.f ? sp0 : sn0), t0));
                float o1 = fabsf(fmaf(fabsf(y1), (y1 > 0.f ? sp1 : sn1), t1));
                float o2 = fabsf(fmaf(fabsf(y2), (y2 > 0.f ? sp0 : sn0), t0));
                float o3 = fabsf(fmaf(fabsf(y3), (y3 > 0.f ? sp1 : sn1), t1));
                __stcs((float2*)(out + (size_t)r0 * OUT + c0),       make_float2(o0, o1));
                __stcs((float2*)(out + (size_t)(r0 + 8) * OUT + c0), make_float2(o2, o3));
            }
        }
    }
}

// ---------------------------------------------------------------------------
extern "C" void kernel_launch(void* const* d_in, const int* in_sizes, int n_in,
                              void* d_out, int out_size)
{
    const float* z  = (const float*)d_in[0];
    const float* Wp = (const float*)d_in[1];
    const float* W1 = (const float*)d_in[2];
    const float* b1 = (const float*)d_in[3];
    const float* W2 = (const float*)d_in[4];
    const float* b2 = (const float*)d_in[5];
    const float* W3 = (const float*)d_in[6];
    const float* b3 = (const float*)d_in[7];
    float* out = (float*)d_out;

    int nrows = in_sizes[0] / LATENT;   // 65536

    cudaFuncSetAttribute(main_kernel,
                         cudaFuncAttributeMaxDynamicSharedMemorySize, SM_TOTAL);

    precompute_kernel<<<OUT, 32>>>(Wp, W1, b1, W2, b2, W3);
    main_kernel<<<nrows / BM, 256, SM_TOTAL>>>(z, Wp, W1, b1, W2, b2, W3, b3,
                                               out, (long)nrows * OUT);
}

// round 10
// speedup vs baseline: 6.3611x; 1.0278x over previous
#include <cuda_runtime.h>
#include <cuda_fp16.h>
#include <cstdint>

#define LATENT 64
#define OUT    128
#define H      32
#define BM     64    // rows per tile
#define PITCH  144   // bytes per smem A row (72 fp16) — conflict-free ldmatrix
#define GRID   296   // 2 persistent CTAs per SM (148 SMs)

// smem layout (dynamic): consts + 2 double-buffered A tile sets (hi+lo)
#define SM_SP    0
#define SM_SN    512
#define SM_B3    1024
#define SM_A0    1536
#define ABUF_SZ  (2 * BM * PITCH)          // hi+lo = 18432
#define SM_TOTAL (SM_A0 + 2 * ABUF_SZ)     // 38400

// Scratch (no device allocation allowed)
__device__ float g_sp[OUT];
__device__ float g_sn[OUT];
__device__ int   g_slow = 0;
// B mma fragments, fp16, exact mma B-operand lane layout:
// u32 index = (((wn*4+g)*4+s)*32 + lane)*2 + reg
__device__ __align__(16) uint32_t g_bf[4 * 4 * 4 * 32 * 2];

// ---------------------------------------------------------------------------
// PTX helpers (family-portable only: ldmatrix + mma.sync)
// ---------------------------------------------------------------------------
__device__ __forceinline__ uint32_t smem_u32(const void* p) {
    uint32_t a;
    asm("{ .reg .u64 t; cvta.to.shared.u64 t, %1; cvt.u32.u64 %0, t; }"
        : "=r"(a) : "l"(p));
    return a;
}
#define LDSM_X4(r0, r1, r2, r3, addr)                                          \
    asm volatile("ldmatrix.sync.aligned.m8n8.x4.shared.b16 {%0,%1,%2,%3}, [%4];" \
                 : "=r"(r0), "=r"(r1), "=r"(r2), "=r"(r3) : "r"(addr))
#define MMA_F16(c, a, b)                                                       \
    asm volatile("mma.sync.aligned.m16n8k16.row.col.f32.f16.f16.f32 "          \
                 "{%0,%1,%2,%3},{%4,%5,%6,%7},{%8,%9},{%0,%1,%2,%3};"          \
                 : "+f"((c)[0]), "+f"((c)[1]), "+f"((c)[2]), "+f"((c)[3])      \
                 : "r"((a)[0]), "r"((a)[1]), "r"((a)[2]), "r"((a)[3]),         \
                   "r"((b)[0]), "r"((b)[1]))

__device__ __forceinline__ uint32_t pack_h2(float a, float b) {
    __half2 h = __floats2half2_rn(a, b);
    return *(uint32_t*)&h;
}

// ---------------------------------------------------------------------------
// Precompute (one block per feature d, 32 lanes):
//  - collapsed slopes sp/sn (valid when b1==b2==0; sets g_slow otherwise)
//  - fp16 B fragments of |Wp| in exact mma B lane layout (lanes 0-15)
// ---------------------------------------------------------------------------
__global__ void precompute_kernel(const float* __restrict__ Wp,
                                  const float* __restrict__ W1,
                                  const float* __restrict__ b1,
                                  const float* __restrict__ W2,
                                  const float* __restrict__ b2,
                                  const float* __restrict__ W3)
{
    const int d    = blockIdx.x;
    const int lane = threadIdx.x;

    // Issue all loads up front
    float  w1v = W1[d * H + lane];
    float  b1v = b1[d * H + lane];
    float  b2v = b2[d * H + lane];
    float  w3  = W3[d * H + lane];
    const float4* w2 = (const float4*)(W2 + ((long)d * H + lane) * H);
    float4 w2v[8];
#pragma unroll
    for (int q = 0; q < H / 4; ++q) w2v[q] = w2[q];

    // B fragments: mma m16n8k16 B operand, lane L holds b[k][n], n = L/4,
    // reg0: k = (L%4)*2 + {0,1}; reg1: k = 8 + (L%4)*2 + {0,1}
    if (lane < 16) {
        const int s  = lane >> 2;
        const int kq = lane & 3;
        const int k0 = s * 16 + kq * 2;
        float f0 = fabsf(Wp[d * LATENT + k0]);
        float f1 = fabsf(Wp[d * LATENT + k0 + 1]);
        float f2 = fabsf(Wp[d * LATENT + k0 + 8]);
        float f3 = fabsf(Wp[d * LATENT + k0 + 9]);
        const int wn    = d >> 5;
        const int g     = (d >> 3) & 3;
        const int flane = (d & 7) * 4 + kq;
        const int idx   = ((((wn * 4 + g) * 4 + s) * 32) + flane) * 2;
        g_bf[idx]     = pack_h2(f0, f1);
        g_bf[idx + 1] = pack_h2(f2, f3);
    }

    int nz = (b1v != 0.f) | (b2v != 0.f);

    float up = 0.f, un = 0.f;
#pragma unroll
    for (int q = 0; q < H / 4; ++q) {
        float wv[4] = {w2v[q].x, w2v[q].y, w2v[q].z, w2v[q].w};
#pragma unroll
        for (int j = 0; j < 4; ++j) {
            float w1h = __shfl_sync(0xffffffffu, w1v, q * 4 + j);
            up = fmaf(wv[j], fmaxf(w1h, 0.f), up);
            un = fmaf(wv[j], fmaxf(-w1h, 0.f), un);
        }
    }
    float tp = w3 * fmaxf(up, 0.f);
    float tn = w3 * fmaxf(un, 0.f);
#pragma unroll
    for (int off = 16; off > 0; off >>= 1) {
        tp += __shfl_down_sync(0xffffffffu, tp, off);
        tn += __shfl_down_sync(0xffffffffu, tn, off);
    }
    unsigned any_nz = __ballot_sync(0xffffffffu, nz);
    if (lane == 0) {
        g_sp[d] = tp;
        g_sn[d] = tn;
        if (any_nz) atomicOr(&g_slow, 1);
    }
}

// ---------------------------------------------------------------------------
// Main: persistent CTAs, software-pipelined tiles.
// fp16 2-term mma.sync GEMM (64 x 128 x 64 per tile) + fused epilogue.
// A double-buffered in smem; B fragments live in registers for the whole CTA.
// ---------------------------------------------------------------------------
__global__ __launch_bounds__(256, 2) void main_kernel(
    const float* __restrict__ z,  const float* __restrict__ Wp,
    const float* __restrict__ W1, const float* __restrict__ b1,
    const float* __restrict__ W2, const float* __restrict__ b2,
    const float* __restrict__ W3, const float* __restrict__ b3,
    float* __restrict__ out, long total, int ntiles)
{
    if (g_slow) {   // exact fallback path (never taken when b1==b2==0)
        for (long idx = (long)blockIdx.x * blockDim.x + threadIdx.x; idx < total;
             idx += (long)gridDim.x * blockDim.x) {
            int n = (int)(idx >> 7);
            int d = (int)(idx & (OUT - 1));
            float y = 0.f;
#pragma unroll
            for (int k = 0; k < LATENT; ++k)
                y = fmaf(z[(long)n * LATENT + k], fabsf(Wp[d * LATENT + k]), y);
            float h1[H];
#pragma unroll
            for (int h = 0; h < H; ++h)
                h1[h] = fmaxf(fmaf(y, W1[d * H + h], b1[d * H + h]), 0.f);
            float x = b3[d];
#pragma unroll 4
            for (int k = 0; k < H; ++k) {
                float t = b2[d * H + k];
                const float* w2 = W2 + ((long)d * H + k) * H;
#pragma unroll
                for (int h = 0; h < H; ++h) t = fmaf(w2[h], h1[h], t);
                x = fmaf(W3[d * H + k], fmaxf(t, 0.f), x);
            }
            out[idx] = fabsf(x);
        }
        return;
    }

    extern __shared__ char smem[];
    const uint32_t sb = smem_u32(smem);
    const int tid  = threadIdx.x;
    const int wid  = tid >> 5;
    const int lane = tid & 31;
    const int wm   = wid >> 2;   // 0..1 -> rows wm*32
    const int wn   = wid & 3;    // 0..3 -> cols wn*32
    const int zrow = tid >> 2;   // 0..63
    const int zseg = tid & 3;    // 0..3 (16 floats each)

    // B fragments: load once, keep in registers for all tiles.
    uint32_t bf[4][4][2];        // [s][g][reg]
#pragma unroll
    for (int g = 0; g < 4; ++g)
#pragma unroll
        for (int s = 0; s < 4; ++s) {
            uint2 t = *(const uint2*)(g_bf + ((wn * 4 + g) * 4 + s) * 64 + lane * 2);
            bf[s][g][0] = t.x; bf[s][g][1] = t.y;
        }

    // Stage epilogue constants
    if (tid < OUT) {
        ((float*)(smem + SM_SP))[tid] = g_sp[tid];
        ((float*)(smem + SM_SN))[tid] = g_sn[tid];
        ((float*)(smem + SM_B3))[tid] = b3[tid];
    }

    // ldmatrix lane offset within an A buffer
    const uint32_t alane = (uint32_t)((wm * 32 + (lane & 15)) * PITCH +
                                      (lane >> 4) * 16);
    // split-store byte offset: zseg indexes 16 floats -> 32 bytes in fp16
    const int zoff = zrow * PITCH + zseg * 32;

    // ---- prologue: load + split tile 0 into buffer 0 ----
    int tile = blockIdx.x;
    float4 v[4];
    {
        const float4* zr = (const float4*)(z + (size_t)(tile * BM + zrow) * LATENT + zseg * 16);
#pragma unroll
        for (int j = 0; j < 4; ++j) v[j] = __ldcs(zr + j);
    }
    int buf = 0;
#pragma unroll
    for (int grp = 0; grp < 2; ++grp) {
        float f[8] = {v[grp*2].x, v[grp*2].y, v[grp*2].z, v[grp*2].w,
                      v[grp*2+1].x, v[grp*2+1].y, v[grp*2+1].z, v[grp*2+1].w};
        uint4 uh, ul;
        uint32_t* uhp = &uh.x;
        uint32_t* ulp = &ul.x;
#pragma unroll
        for (int e = 0; e < 4; ++e) {
            __half2 h2 = __floats2half2_rn(f[e*2], f[e*2+1]);
            float2 hf = __half22float2(h2);
            uhp[e] = *(uint32_t*)&h2;
            ulp[e] = pack_h2(f[e*2] - hf.x, f[e*2+1] - hf.y);
        }
        *(uint4*)(smem + SM_A0 + zoff + grp * 16) = uh;
        *(uint4*)(smem + SM_A0 + BM * PITCH + zoff + grp * 16) = ul;
    }
    __syncthreads();

    // ---- pipelined tile loop ----
    while (true) {
        const int next = tile + GRID;
        const bool has_next = next < ntiles;

        // Issue next tile's global loads early (latency hidden by MMA below)
        if (has_next) {
            const float4* zr = (const float4*)(z + (size_t)(next * BM + zrow) * LATENT + zseg * 16);
#pragma unroll
            for (int j = 0; j < 4; ++j) v[j] = __ldcs(zr + j);
        }

        // MMA from A[buf]
        const uint32_t ahi = sb + SM_A0 + (uint32_t)buf * ABUF_SZ + alane;
        const uint32_t alo = ahi + BM * PITCH;

        float acc[2][4][4];
#pragma unroll
        for (int f = 0; f < 2; ++f)
#pragma unroll
            for (int g = 0; g < 4; ++g)
#pragma unroll
                for (int e = 0; e < 4; ++e) acc[f][g][e] = 0.f;

#pragma unroll
        for (int s = 0; s < 4; ++s) {
            uint32_t ah[2][4], al[2][4];
#pragma unroll
            for (int f = 0; f < 2; ++f)
                LDSM_X4(ah[f][0], ah[f][1], ah[f][2], ah[f][3],
                        ahi + f * 16 * PITCH + s * 32);
#pragma unroll
            for (int f = 0; f < 2; ++f)
                LDSM_X4(al[f][0], al[f][1], al[f][2], al[f][3],
                        alo + f * 16 * PITCH + s * 32);
#pragma unroll
            for (int f = 0; f < 2; ++f)
#pragma unroll
                for (int g = 0; g < 4; ++g)
                    MMA_F16(acc[f][g], ah[f], bf[s][g]);
#pragma unroll
            for (int f = 0; f < 2; ++f)
#pragma unroll
                for (int g = 0; g < 4; ++g)
                    MMA_F16(acc[f][g], al[f], bf[s][g]);
        }

        // Split next tile into the other buffer (independent of acc)
        if (has_next) {
#pragma unroll
            for (int grp = 0; grp < 2; ++grp) {
                float f[8] = {v[grp*2].x, v[grp*2].y, v[grp*2].z, v[grp*2].w,
                              v[grp*2+1].x, v[grp*2+1].y, v[grp*2+1].z, v[grp*2+1].w};
                uint4 uh, ul;
                uint32_t* uhp = &uh.x;
                uint32_t* ulp = &ul.x;
#pragma unroll
                for (int e = 0; e < 4; ++e) {
                    __half2 h2 = __floats2half2_rn(f[e*2], f[e*2+1]);
                    float2 hf = __half22float2(h2);
                    uhp[e] = *(uint32_t*)&h2;
                    ulp[e] = pack_h2(f[e*2] - hf.x, f[e*2+1] - hf.y);
                }
                uint32_t base = SM_A0 + (uint32_t)(buf ^ 1) * ABUF_SZ + zoff + grp * 16;
                *(uint4*)(smem + base) = uh;
                *(uint4*)(smem + base + BM * PITCH) = ul;
            }
        }

        // Fused epilogue for current tile (streaming stores)
        {
            const int brow = tile * BM;
            const int qrow = lane >> 2;
            const int qcol = 2 * (lane & 3);
            const float* sps = (const float*)(smem + SM_SP);
            const float* sns = (const float*)(smem + SM_SN);
            const float* b3s = (const float*)(smem + SM_B3);
#pragma unroll
            for (int g = 0; g < 4; ++g) {
                const int c0 = wn * 32 + g * 8 + qcol;
                float sp0 = sps[c0], sp1 = sps[c0 + 1];
                float sn0 = sns[c0], sn1 = sns[c0 + 1];
                float t0  = b3s[c0], t1  = b3s[c0 + 1];
#pragma unroll
                for (int f = 0; f < 2; ++f) {
                    const int r0 = brow + wm * 32 + f * 16 + qrow;
                    float y0 = acc[f][g][0], y1 = acc[f][g][1];
                    float y2 = acc[f][g][2], y3 = acc[f][g][3];
                    float o0 = fabsf(fmaf(fabsf(y0), (y0 > 0.f ? sp0 : sn0), t0));
                    float o1 = fabsf(fmaf(fabsf(y1), (y1 > 0.f ? sp1 : sn1), t1));
                    float o2 = fabsf(fmaf(fabsf(y2), (y2 > 0.f ? sp0 : sn0), t0));
                    float o3 = fabsf(fmaf(fabsf(y3), (y3 > 0.f ? sp1 : sn1), t1));
                    __stcs((float2*)(out + (size_t)r0 * OUT + c0),       make_float2(o0, o1));
                    __stcs((float2*)(out + (size_t)(r0 + 8) * OUT + c0), make_float2(o2, o3));
                }
            }
        }

        if (!has_next) break;
        __syncthreads();          // next buffer fully written; old reads done
        buf ^= 1;
        tile = next;
    }
}

// ---------------------------------------------------------------------------
extern "C" void kernel_launch(void* const* d_in, const int* in_sizes, int n_in,
                              void* d_out, int out_size)
{
    const float* z  = (const float*)d_in[0];
    const float* Wp = (const float*)d_in[1];
    const float* W1 = (const float*)d_in[2];
    const float* b1 = (const float*)d_in[3];
    const float* W2 = (const float*)d_in[4];
    const float* b2 = (const float*)d_in[5];
    const float* W3 = (const float*)d_in[6];
    const float* b3 = (const float*)d_in[7];
    float* out = (float*)d_out;

    int nrows  = in_sizes[0] / LATENT;   // 65536
    int ntiles = nrows / BM;             // 1024

    cudaFuncSetAttribute(main_kernel,
                         cudaFuncAttributeMaxDynamicSharedMemorySize, SM_TOTAL);

    precompute_kernel<<<OUT, 32>>>(Wp, W1, b1, W2, b2, W3);
    main_kernel<<<GRID, 256, SM_TOTAL>>>(z, Wp, W1, b1, W2, b2, W3, b3,
                                         out, (long)nrows * OUT, ntiles);
}

// round 11
// speedup vs baseline: 6.9526x; 1.0930x over previous
#include <cuda_runtime.h>
#include <cuda_fp16.h>
#include <cstdint>

#define LATENT 64
#define OUT    128
#define H      32
#define BM     64    // rows per CTA
#define PITCH  144   // bytes per smem A row (72 fp16) — conflict-free ldmatrix

// smem layout (dynamic)
#define SM_SP    0
#define SM_SN    512
#define SM_B3    1024
#define SM_AHI   1536
#define SM_TOTAL (SM_AHI + BM * PITCH)   // 10752

// Scratch (no device allocation allowed)
__device__ float g_sp[OUT];
__device__ float g_sn[OUT];
__device__ int   g_slow = 0;
// B mma fragments, fp16, exact mma B-operand lane layout:
// u32 index = (((wn*4+g)*4+s)*32 + lane)*2 + reg
__device__ __align__(16) uint32_t g_bf[4 * 4 * 4 * 32 * 2];

// ---------------------------------------------------------------------------
// PTX helpers (family-portable only: ldmatrix + mma.sync)
// ---------------------------------------------------------------------------
__device__ __forceinline__ uint32_t smem_u32(const void* p) {
    uint32_t a;
    asm("{ .reg .u64 t; cvta.to.shared.u64 t, %1; cvt.u32.u64 %0, t; }"
        : "=r"(a) : "l"(p));
    return a;
}
#define LDSM_X4(r0, r1, r2, r3, addr)                                          \
    asm volatile("ldmatrix.sync.aligned.m8n8.x4.shared.b16 {%0,%1,%2,%3}, [%4];" \
                 : "=r"(r0), "=r"(r1), "=r"(r2), "=r"(r3) : "r"(addr))
#define MMA_F16(c, a, b)                                                       \
    asm volatile("mma.sync.aligned.m16n8k16.row.col.f32.f16.f16.f32 "          \
                 "{%0,%1,%2,%3},{%4,%5,%6,%7},{%8,%9},{%0,%1,%2,%3};"          \
                 : "+f"((c)[0]), "+f"((c)[1]), "+f"((c)[2]), "+f"((c)[3])      \
                 : "r"((a)[0]), "r"((a)[1]), "r"((a)[2]), "r"((a)[3]),         \
                   "r"((b)[0]), "r"((b)[1]))

__device__ __forceinline__ uint32_t pack_h2(float a, float b) {
    __half2 h = __floats2half2_rn(a, b);
    return *(uint32_t*)&h;
}

// ---------------------------------------------------------------------------
// Precompute (one block per feature d, 32 lanes):
//  - collapsed slopes sp/sn (valid when b1==b2==0; sets g_slow otherwise)
//  - fp16 B fragments of |Wp| in exact mma B lane layout (lanes 0-15)
// ---------------------------------------------------------------------------
__global__ void precompute_kernel(const float* __restrict__ Wp,
                                  const float* __restrict__ W1,
                                  const float* __restrict__ b1,
                                  const float* __restrict__ W2,
                                  const float* __restrict__ b2,
                                  const float* __restrict__ W3)
{
    const int d    = blockIdx.x;
    const int lane = threadIdx.x;

    // Issue all loads up front
    float  w1v = W1[d * H + lane];
    float  b1v = b1[d * H + lane];
    float  b2v = b2[d * H + lane];
    float  w3  = W3[d * H + lane];
    const float4* w2 = (const float4*)(W2 + ((long)d * H + lane) * H);
    float4 w2v[8];
#pragma unroll
    for (int q = 0; q < H / 4; ++q) w2v[q] = w2[q];

    // B fragments: mma m16n8k16 B operand, lane L holds b[k][n], n = L/4,
    // reg0: k = (L%4)*2 + {0,1}; reg1: k = 8 + (L%4)*2 + {0,1}
    if (lane < 16) {
        const int s  = lane >> 2;
        const int kq = lane & 3;
        const int k0 = s * 16 + kq * 2;
        float f0 = fabsf(Wp[d * LATENT + k0]);
        float f1 = fabsf(Wp[d * LATENT + k0 + 1]);
        float f2 = fabsf(Wp[d * LATENT + k0 + 8]);
        float f3 = fabsf(Wp[d * LATENT + k0 + 9]);
        const int wn    = d >> 5;
        const int g     = (d >> 3) & 3;
        const int flane = (d & 7) * 4 + kq;
        const int idx   = ((((wn * 4 + g) * 4 + s) * 32) + flane) * 2;
        g_bf[idx]     = pack_h2(f0, f1);
        g_bf[idx + 1] = pack_h2(f2, f3);
    }

    int nz = (b1v != 0.f) | (b2v != 0.f);

    float up = 0.f, un = 0.f;
#pragma unroll
    for (int q = 0; q < H / 4; ++q) {
        float wv[4] = {w2v[q].x, w2v[q].y, w2v[q].z, w2v[q].w};
#pragma unroll
        for (int j = 0; j < 4; ++j) {
            float w1h = __shfl_sync(0xffffffffu, w1v, q * 4 + j);
            up = fmaf(wv[j], fmaxf(w1h, 0.f), up);
            un = fmaf(wv[j], fmaxf(-w1h, 0.f), un);
        }
    }
    float tp = w3 * fmaxf(up, 0.f);
    float tn = w3 * fmaxf(un, 0.f);
#pragma unroll
    for (int off = 16; off > 0; off >>= 1) {
        tp += __shfl_down_sync(0xffffffffu, tp, off);
        tn += __shfl_down_sync(0xffffffffu, tn, off);
    }
    unsigned any_nz = __ballot_sync(0xffffffffu, nz);
    if (lane == 0) {
        g_sp[d] = tp;
        g_sn[d] = tn;
        if (any_nz) atomicOr(&g_slow, 1);
    }
}

// ---------------------------------------------------------------------------
// Main: single-term fp16 mma.sync GEMM (BM=64 x 128, K=64) + fused epilogue.
// A = rn(z) fp16 via smem+ldmatrix; B = fp16 fragments streamed from gmem.
// 8 warps, warp tile 32(m) x 32(n), 3 CTAs/SM.
// ---------------------------------------------------------------------------
__global__ __launch_bounds__(256, 3) void main_kernel(
    const float* __restrict__ z,  const float* __restrict__ Wp,
    const float* __restrict__ W1, const float* __restrict__ b1,
    const float* __restrict__ W2, const float* __restrict__ b2,
    const float* __restrict__ W3, const float* __restrict__ b3,
    float* __restrict__ out, long total)
{
    if (g_slow) {   // exact fallback path (never taken when b1==b2==0)
        for (long idx = (long)blockIdx.x * blockDim.x + threadIdx.x; idx < total;
             idx += (long)gridDim.x * blockDim.x) {
            int n = (int)(idx >> 7);
            int d = (int)(idx & (OUT - 1));
            float y = 0.f;
#pragma unroll
            for (int k = 0; k < LATENT; ++k)
                y = fmaf(z[(long)n * LATENT + k], fabsf(Wp[d * LATENT + k]), y);
            float h1[H];
#pragma unroll
            for (int h = 0; h < H; ++h)
                h1[h] = fmaxf(fmaf(y, W1[d * H + h], b1[d * H + h]), 0.f);
            float x = b3[d];
#pragma unroll 4
            for (int k = 0; k < H; ++k) {
                float t = b2[d * H + k];
                const float* w2 = W2 + ((long)d * H + k) * H;
#pragma unroll
                for (int h = 0; h < H; ++h) t = fmaf(w2[h], h1[h], t);
                x = fmaf(W3[d * H + k], fmaxf(t, 0.f), x);
            }
            out[idx] = fabsf(x);
        }
        return;
    }

    extern __shared__ char smem[];
    const uint32_t sb = smem_u32(smem);
    const int tid  = threadIdx.x;
    const int wid  = tid >> 5;
    const int lane = tid & 31;
    const int wm   = wid >> 2;   // 0..1 -> rows wm*32
    const int wn   = wid & 3;    // 0..3 -> cols wn*32
    const int brow = blockIdx.x * BM;

    // z tile loads first (deepest latency): 64 rows x 64 f32.
    const int zrow = tid >> 2;
    const int zseg = tid & 3;
    const float4* zr = (const float4*)(z + (size_t)(brow + zrow) * LATENT + zseg * 16);
    float4 v[4];
#pragma unroll
    for (int j = 0; j < 4; ++j) v[j] = __ldcs(zr + j);

    // Prefetch B fragments for s=0 (gmem, L2/L1-hot).
    // Strides (u32): wn:1024, g:256, s:64, lane:2.
    const uint32_t* bfbase = g_bf + (size_t)wn * 1024 + lane * 2;
    uint32_t bcur[4][2], bnxt[4][2];
#pragma unroll
    for (int g = 0; g < 4; ++g) {
        uint2 t = *(const uint2*)(bfbase + g * 256);
        bcur[g][0] = t.x; bcur[g][1] = t.y;
    }

    // Stage epilogue constants
    if (tid < OUT) {
        ((float*)(smem + SM_SP))[tid] = g_sp[tid];
        ((float*)(smem + SM_SN))[tid] = g_sn[tid];
        ((float*)(smem + SM_B3))[tid] = b3[tid];
    }

    // fp16 convert of z into smem (single term: A = rn(z))
    {
        uint4 uh0, uh1;
        uh0.x = pack_h2(v[0].x, v[0].y); uh0.y = pack_h2(v[0].z, v[0].w);
        uh0.z = pack_h2(v[1].x, v[1].y); uh0.w = pack_h2(v[1].z, v[1].w);
        uh1.x = pack_h2(v[2].x, v[2].y); uh1.y = pack_h2(v[2].z, v[2].w);
        uh1.z = pack_h2(v[3].x, v[3].y); uh1.w = pack_h2(v[3].z, v[3].w);
        int off = zrow * PITCH + zseg * 32;   // 16 floats -> 32 bytes fp16
        *(uint4*)(smem + SM_AHI + off)      = uh0;
        *(uint4*)(smem + SM_AHI + off + 16) = uh1;
    }
    __syncthreads();

    // ldmatrix lane base address (A)
    const uint32_t aoff = sb + SM_AHI + (uint32_t)((wm * 32 + (lane & 15)) * PITCH +
                                                   (lane >> 4) * 16);

    float acc[2][4][4];
#pragma unroll
    for (int f = 0; f < 2; ++f)
#pragma unroll
        for (int g = 0; g < 4; ++g)
#pragma unroll
            for (int e = 0; e < 4; ++e) acc[f][g][e] = 0.f;

    // K=64 in 4 k16 steps; B frags double-buffered from gmem.
#pragma unroll
    for (int s = 0; s < 4; ++s) {
        if (s < 3) {
#pragma unroll
            for (int g = 0; g < 4; ++g) {
                uint2 t = *(const uint2*)(bfbase + (s + 1) * 64 + g * 256);
                bnxt[g][0] = t.x; bnxt[g][1] = t.y;
            }
        }
        uint32_t ah[2][4];
#pragma unroll
        for (int f = 0; f < 2; ++f)
            LDSM_X4(ah[f][0], ah[f][1], ah[f][2], ah[f][3],
                    aoff + f * 16 * PITCH + s * 32);
#pragma unroll
        for (int f = 0; f < 2; ++f)
#pragma unroll
            for (int g = 0; g < 4; ++g)
                MMA_F16(acc[f][g], ah[f], bcur[g]);
        if (s < 3) {
#pragma unroll
            for (int g = 0; g < 4; ++g) {
                bcur[g][0] = bnxt[g][0]; bcur[g][1] = bnxt[g][1];
            }
        }
    }

    // Fused epilogue straight from fragments (streaming stores).
    {
        const int qrow = lane >> 2;
        const int qcol = 2 * (lane & 3);
        const float* sps = (const float*)(smem + SM_SP);
        const float* sns = (const float*)(smem + SM_SN);
        const float* b3s = (const float*)(smem + SM_B3);
#pragma unroll
        for (int g = 0; g < 4; ++g) {
            const int c0 = wn * 32 + g * 8 + qcol;
            float sp0 = sps[c0], sp1 = sps[c0 + 1];
            float sn0 = sns[c0], sn1 = sns[c0 + 1];
            float t0  = b3s[c0], t1  = b3s[c0 + 1];
#pragma unroll
            for (int f = 0; f < 2; ++f) {
                const int r0 = brow + wm * 32 + f * 16 + qrow;
                float y0 = acc[f][g][0], y1 = acc[f][g][1];
                float y2 = acc[f][g][2], y3 = acc[f][g][3];
                float o0 = fabsf(fmaf(fabsf(y0), (y0 > 0.f ? sp0 : sn0), t0));
                float o1 = fabsf(fmaf(fabsf(y1), (y1 > 0.f ? sp1 : sn1), t1));
                float o2 = fabsf(fmaf(fabsf(y2), (y2 > 0.f ? sp0 : sn0), t0));
                float o3 = fabsf(fmaf(fabsf(y3), (y3 > 0.f ? sp1 : sn1), t1));
                __stcs((float2*)(out + (size_t)r0 * OUT + c0),       make_float2(o0, o1));
                __stcs((float2*)(out + (size_t)(r0 + 8) * OUT + c0), make_float2(o2, o3));
            }
        }
    }
}

// ---------------------------------------------------------------------------
extern "C" void kernel_launch(void* const* d_in, const int* in_sizes, int n_in,
                              void* d_out, int out_size)
{
    const float* z  = (const float*)d_in[0];
    const float* Wp = (const float*)d_in[1];
    const float* W1 = (const float*)d_in[2];
    const float* b1 = (const float*)d_in[3];
    const float* W2 = (const float*)d_in[4];
    const float* b2 = (const float*)d_in[5];
    const float* W3 = (const float*)d_in[6];
    const float* b3 = (const float*)d_in[7];
    float* out = (float*)d_out;

    int nrows = in_sizes[0] / LATENT;   // 65536

    cudaFuncSetAttribute(main_kernel,
                         cudaFuncAttributeMaxDynamicSharedMemorySize, SM_TOTAL);

    precompute_kernel<<<OUT, 32>>>(Wp, W1, b1, W2, b2, W3);
    main_kernel<<<nrows / BM, 256, SM_TOTAL>>>(z, Wp, W1, b1, W2, b2, W3, b3,
                                               out, (long)nrows * OUT);
}